// round 12
// baseline (speedup 1.0000x reference)
#include <cuda_runtime.h>
#include <cuda_bf16.h>
#include <cuda_fp16.h>
#include <cstdint>

#define NN   50000
#define NE   1600000
#define D    128
#define NCLS 6
#define NBLK 49          // ceil(NN / 1024) scan blocks

// ---------------- scratch (static device globals; no runtime allocation) ----
__device__ float  g_agg12[NN * 12];
__device__ float  g_hA[(size_t)NN * D];
__device__ float  g_hB[(size_t)NN * D];
__device__ __half g_h16A[(size_t)NN * D];
__device__ __half g_h16B[(size_t)NN * D];
__device__ int    g_counts[NN];
__device__ int    g_rowptr[NN + 1];
__device__ int    g_cursor[NN];
__device__ int    g_col[NE];
__device__ volatile int g_scan_val[64];
__device__ volatile int g_scan_flag[64];
__device__ int    g_is64;   // 1 if edge_index really is int64, 0 if int32

// ---------------- small helpers ---------------------------------------------
__device__ __forceinline__ uint32_t smem_to_u32(const void* p) {
    uint32_t a;
    asm("{ .reg .u64 t; cvta.to.shared.u64 t, %1; cvt.u32.u64 %0, t; }"
        : "=r"(a) : "l"(p));
    return a;
}
__device__ __forceinline__ uint32_t lds32(uint32_t addr) {
    uint32_t v;
    asm volatile("ld.shared.b32 %0, [%1];" : "=r"(v) : "r"(addr));
    return v;
}
__device__ __forceinline__ void sts32(uint32_t addr, uint32_t v) {
    asm volatile("st.shared.b32 [%0], %1;" :: "r"(addr), "r"(v) : "memory");
}
// split two fp32 into bf16 hi/lo packed pairs
__device__ __forceinline__ void split2(float x, float y, uint32_t& hi, uint32_t& lo) {
    __nv_bfloat16 xh = __float2bfloat16(x), yh = __float2bfloat16(y);
    float xr = x - __bfloat162float(xh);
    float yr = y - __bfloat162float(yh);
    __nv_bfloat16 xl = __float2bfloat16(xr), yl = __float2bfloat16(yr);
    hi = ((uint32_t)__bfloat16_as_ushort(yh) << 16) | __bfloat16_as_ushort(xh);
    lo = ((uint32_t)__bfloat16_as_ushort(yl) << 16) | __bfloat16_as_ushort(xl);
}
__device__ __forceinline__ void mma16816(float* c, const uint32_t* a, const uint32_t* b) {
    asm volatile(
        "mma.sync.aligned.m16n8k16.row.col.f32.bf16.bf16.f32 "
        "{%0,%1,%2,%3},{%4,%5,%6,%7},{%8,%9},{%0,%1,%2,%3};"
        : "+f"(c[0]), "+f"(c[1]), "+f"(c[2]), "+f"(c[3])
        : "r"(a[0]), "r"(a[1]), "r"(a[2]), "r"(a[3]), "r"(b[0]), "r"(b[1]));
}
__device__ __forceinline__ void acc_h2(float4& a, uint2 p) {
    __half2 h0 = *reinterpret_cast<__half2*>(&p.x);
    __half2 h1 = *reinterpret_cast<__half2*>(&p.y);
    float2 f0 = __half22float2(h0);
    float2 f1 = __half22float2(h1);
    a.x += f0.x; a.y += f0.y; a.z += f1.x; a.w += f1.y;
}

// ---------------- smem tile layouts ------------------------------------------
#define KS 136                       // bf16 elems per row (padded)
__device__ __forceinline__ uint32_t a_off(int r, int k) {
    return (uint32_t)(r * KS + k) * 2;
}
// W tile: [n][k] with XOR swizzle on k bits 1..2 keyed by (n>>3)&3.
__device__ __forceinline__ uint32_t wt_off(int n, int k) {
    return (uint32_t)(n * KS + (k ^ ((((unsigned)n >> 3) & 3) << 1))) * 2;
}

#define SM_AHI   0
#define SM_ALO   34816
#define SM_W1HI  69632
#define SM_W1LO  104448
#define SM_W2HI  139264
#define SM_W2LO  174080
#define SM_PAR   208896              // 640 floats: b1|b2|sc|mn|bt
#define SM_TOTAL 211456

// ---------------- edge dtype detect + zero counts + reset scan flags --------
__global__ void detect_zero_kernel(const void* ei) {
    int i = blockIdx.x * blockDim.x + threadIdx.x;
    if (i < NN) g_counts[i] = 0;
    if (i < 64) { g_scan_flag[i] = 0; g_scan_val[i] = 0; }
    if (i == 0) {
        const long long* p = (const long long*)ei;
        int ok = 1;
        for (int j = 0; j < 64; j++) {
            long long v = p[j];
            if (v < 0 || v >= NN) { ok = 0; break; }
        }
        g_is64 = ok;
    }
}
__device__ __forceinline__ int edge_idx(const void* ei, long long pos, int is64) {
    if (is64) return (int)((const long long*)ei)[pos];
    return ((const int*)ei)[pos];
}

// ---------------- CSR build --------------------------------------------------
__global__ void hist_kernel(const void* __restrict__ ei) {
    int e = blockIdx.x * blockDim.x + threadIdx.x;
    if (e >= NE) return;
    const int is64 = g_is64;
    int dst = edge_idx(ei, (long long)NE + e, is64);
    if ((unsigned)dst < NN) atomicAdd(&g_counts[dst], 1);
}

// single-kernel exclusive scan with decoupled lookback (49 blocks co-resident)
__global__ void scan_lookback_kernel() {
    __shared__ int sh[1024];
    __shared__ int prefix_s;
    int b = blockIdx.x;
    int i = b * 1024 + threadIdx.x;
    int v = (i < NN) ? g_counts[i] : 0;
    sh[threadIdx.x] = v;
    __syncthreads();
#pragma unroll
    for (int off = 1; off < 1024; off <<= 1) {
        int t = (threadIdx.x >= off) ? sh[threadIdx.x - off] : 0;
        __syncthreads();
        sh[threadIdx.x] += t;
        __syncthreads();
    }
    int total = sh[1023];
    if (threadIdx.x == 0) {
        g_scan_val[b] = total;
        __threadfence();
        g_scan_flag[b] = 1;
        int pre = 0;
        for (int p = b - 1; p >= 0; p--) {
            while (g_scan_flag[p] == 0) {}
            pre += g_scan_val[p];
        }
        prefix_s = pre;
        if (b == NBLK - 1) g_rowptr[NN] = pre + total;
    }
    __syncthreads();
    if (i < NN) {
        int excl = prefix_s + sh[threadIdx.x] - v;
        g_rowptr[i] = excl;
        g_cursor[i] = excl;
    }
}

__global__ void fill_kernel(const void* __restrict__ ei) {
    int e = blockIdx.x * blockDim.x + threadIdx.x;
    if (e >= NE) return;
    const int is64 = g_is64;
    int src = edge_idx(ei, e, is64);
    int dst = edge_idx(ei, (long long)NE + e, is64);
    if ((unsigned)src >= NN || (unsigned)dst >= NN) return;
    int pos = atomicAdd(&g_cursor[dst], 1);
    g_col[pos] = src;
}

// ---------------- layer-1 gather (12 features) -------------------------------
__global__ void gather12_kernel(const float* __restrict__ x) {
    int n = (blockIdx.x * blockDim.x + threadIdx.x) >> 5;
    if (n >= NN) return;
    int lane = threadIdx.x & 31;
    int beg = g_rowptr[n], end = g_rowptr[n + 1];
    float acc = (lane < 12) ? x[(size_t)n * 12 + lane] : 0.f;
    for (int e = beg; e < end; e++) {
        int s = g_col[e];
        if (lane < 12) acc += x[(size_t)s * 12 + lane];
    }
    if (lane < 12) g_agg12[(size_t)n * 12 + lane] = acc;
}

// ============================================================================
// mma.sync fused MLP: 128-row tile per CTA, 512 threads (16 warps, 4x4 grid).
// Warp (wr, wc): rows [32wr,+32) as 2 m16 tiles, cols [32wc,+32) as 4 n8 tiles.
// bf16 hi/lo split, 3 passes, fp32 accum.
// If h16in != nullptr: A = hin[row] + sum_{src} h16in[src]  (fused GIN gather,
// CSR from g_rowptr/g_col; ping-pong buffers make this race-free).
// head==0: out = BN(relu(relu(A@W1+b1)@W2+b2)), + fp16 copy to out16.
// head==1: fc1 (mma) + fc2 (SIMT).
// ============================================================================
__device__ __forceinline__ void gemm_split(
    uint32_t aHi, uint32_t aLo, uint32_t wHi, uint32_t wLo,
    int r0, int cc, int n0, int lane, float acc[2][4][4], int kpad) {
#pragma unroll 2
    for (int kb = 0; kb < kpad; kb += 16) {
        uint32_t ah[2][4], al[2][4];
#pragma unroll
        for (int m = 0; m < 2; m++) {
            int rm = r0 + m * 16;
            ah[m][0] = lds32(aHi + a_off(rm,     kb + cc));
            ah[m][1] = lds32(aHi + a_off(rm + 8, kb + cc));
            ah[m][2] = lds32(aHi + a_off(rm,     kb + cc + 8));
            ah[m][3] = lds32(aHi + a_off(rm + 8, kb + cc + 8));
            al[m][0] = lds32(aLo + a_off(rm,     kb + cc));
            al[m][1] = lds32(aLo + a_off(rm + 8, kb + cc));
            al[m][2] = lds32(aLo + a_off(rm,     kb + cc + 8));
            al[m][3] = lds32(aLo + a_off(rm + 8, kb + cc + 8));
        }
#pragma unroll
        for (int t = 0; t < 4; t++) {
            int nl = n0 + t * 8 + (lane >> 2);
            uint32_t bh[2], bl[2];
            bh[0] = lds32(wHi + wt_off(nl, kb + cc));
            bh[1] = lds32(wHi + wt_off(nl, kb + cc + 8));
            bl[0] = lds32(wLo + wt_off(nl, kb + cc));
            bl[1] = lds32(wLo + wt_off(nl, kb + cc + 8));
            mma16816(acc[0][t], ah[0], bh);
            mma16816(acc[1][t], ah[1], bh);
            mma16816(acc[0][t], al[0], bh);
            mma16816(acc[1][t], al[1], bh);
            mma16816(acc[0][t], ah[0], bl);
            mma16816(acc[1][t], ah[1], bl);
        }
    }
}

template <int KIN, int KPAD>
__global__ __launch_bounds__(512, 1) void mlp_mma(
    const float* __restrict__ A,
    const __half* __restrict__ h16in,   // if set: fused gather (KIN must be 128)
    const float* __restrict__ W1, const float* __restrict__ b1,
    const float* __restrict__ W2, const float* __restrict__ b2,
    const float* __restrict__ gamma, const float* __restrict__ beta,
    const float* __restrict__ mean, const float* __restrict__ var,
    float* __restrict__ out, __half* __restrict__ out16, int head) {
    extern __shared__ char smem[];
    const uint32_t sb = smem_to_u32(smem);
    const int tid = threadIdx.x;
    const int lane = tid & 31;
    const int wid = tid >> 5;
    const int wr = wid >> 2, wc = wid & 3;    // 4 x 4 warps
    const int row0 = blockIdx.x * 128;

    const uint32_t AHI = sb + SM_AHI, ALO = sb + SM_ALO;
    const uint32_t W1HI = sb + SM_W1HI, W1LO = sb + SM_W1LO;
    const uint32_t W2HI = sb + SM_W2HI, W2LO = sb + SM_W2LO;
    float* par = (float*)(smem + SM_PAR);   // b1[128] b2[128] sc[128] mn[128] bt[128]

    // ---- stage A tiles ----
    if (h16in != nullptr) {
        // fused GIN gather: warp handles 8 rows; lane owns 4 features (fo..fo+3)
        const int fo = lane * 4;
#pragma unroll 1
        for (int i = 0; i < 8; i++) {
            int r = wid * 8 + i;
            int n = row0 + r;
            float4 acc = make_float4(0.f, 0.f, 0.f, 0.f);
            if (n < NN) {
                acc = *reinterpret_cast<const float4*>(A + (size_t)n * D + fo);
                int e = g_rowptr[n], end = g_rowptr[n + 1];
                float4 acc2 = make_float4(0.f, 0.f, 0.f, 0.f);
                for (; e + 7 < end; e += 8) {
                    uint2 p0 = *reinterpret_cast<const uint2*>(h16in + (size_t)g_col[e]     * D + fo);
                    uint2 p1 = *reinterpret_cast<const uint2*>(h16in + (size_t)g_col[e + 1] * D + fo);
                    uint2 p2 = *reinterpret_cast<const uint2*>(h16in + (size_t)g_col[e + 2] * D + fo);
                    uint2 p3 = *reinterpret_cast<const uint2*>(h16in + (size_t)g_col[e + 3] * D + fo);
                    uint2 p4 = *reinterpret_cast<const uint2*>(h16in + (size_t)g_col[e + 4] * D + fo);
                    uint2 p5 = *reinterpret_cast<const uint2*>(h16in + (size_t)g_col[e + 5] * D + fo);
                    uint2 p6 = *reinterpret_cast<const uint2*>(h16in + (size_t)g_col[e + 6] * D + fo);
                    uint2 p7 = *reinterpret_cast<const uint2*>(h16in + (size_t)g_col[e + 7] * D + fo);
                    acc_h2(acc, p0);  acc_h2(acc2, p1);
                    acc_h2(acc, p2);  acc_h2(acc2, p3);
                    acc_h2(acc, p4);  acc_h2(acc2, p5);
                    acc_h2(acc, p6);  acc_h2(acc2, p7);
                }
                for (; e < end; e++) {
                    uint2 p = *reinterpret_cast<const uint2*>(h16in + (size_t)g_col[e] * D + fo);
                    acc_h2(acc, p);
                }
                acc.x += acc2.x; acc.y += acc2.y; acc.z += acc2.z; acc.w += acc2.w;
            }
            uint32_t h0, l0, h1, l1;
            split2(acc.x, acc.y, h0, l0);
            split2(acc.z, acc.w, h1, l1);
            sts32(AHI + a_off(r, fo),     h0);
            sts32(AHI + a_off(r, fo + 2), h1);
            sts32(ALO + a_off(r, fo),     l0);
            sts32(ALO + a_off(r, fo + 2), l1);
        }
    } else {
        int r = tid >> 2, q = tid & 3;
        int gr = row0 + r;
        const float* ar = A + (size_t)gr * KIN;
        bool ok = gr < NN;
#pragma unroll
        for (int j = 0; j < KPAD / 16; j++) {
            int k = q * (KPAD / 4) + j * 4;
            float4 v = make_float4(0.f, 0.f, 0.f, 0.f);
            if (ok) {
                if (k + 3 < KIN) v = *reinterpret_cast<const float4*>(ar + k);
                else {
                    if (k     < KIN) v.x = ar[k];
                    if (k + 1 < KIN) v.y = ar[k + 1];
                    if (k + 2 < KIN) v.z = ar[k + 2];
                    if (k + 3 < KIN) v.w = ar[k + 3];
                }
            }
            uint32_t h0, l0, h1, l1;
            split2(v.x, v.y, h0, l0);
            split2(v.z, v.w, h1, l1);
            sts32(AHI + a_off(r, k),     h0);
            sts32(AHI + a_off(r, k + 2), h1);
            sts32(ALO + a_off(r, k),     l0);
            sts32(ALO + a_off(r, k + 2), l1);
        }
    }
    // ---- stage W1 transposed [n][k] hi/lo ----
    {
        int n = tid & 127;
        int ko = (tid >> 7) * 2;   // 0,2,4,6
        for (int kk = 0; kk < KPAD; kk += 8) {
            int k = kk + ko;
            float v0 = (k     < KIN) ? __ldg(W1 + (size_t)k * D + n) : 0.f;
            float v1 = (k + 1 < KIN) ? __ldg(W1 + (size_t)(k + 1) * D + n) : 0.f;
            uint32_t hi, lo;
            split2(v0, v1, hi, lo);
            sts32(W1HI + wt_off(n, k), hi);
            sts32(W1LO + wt_off(n, k), lo);
        }
    }
    // ---- stage W2 ----
    if (!head) {
        int n = tid & 127;
        int ko = (tid >> 7) * 2;
        for (int kk = 0; kk < 128; kk += 8) {
            int k = kk + ko;
            float v0 = __ldg(W2 + (size_t)k * D + n);
            float v1 = __ldg(W2 + (size_t)(k + 1) * D + n);
            uint32_t hi, lo;
            split2(v0, v1, hi, lo);
            sts32(W2HI + wt_off(n, k), hi);
            sts32(W2LO + wt_off(n, k), lo);
        }
    } else {
        float* w2f = (float*)(smem + SM_W2HI);
        for (int i = tid; i < D * NCLS; i += 512) w2f[i] = __ldg(W2 + i);
    }
    // ---- stage params ----
    if (tid < 128) {
        par[tid] = __ldg(b1 + tid);
        if (!head) {
            par[128 + tid] = __ldg(b2 + tid);
            par[256 + tid] = __ldg(gamma + tid) * rsqrtf(__ldg(var + tid) + 1e-5f);
            par[384 + tid] = __ldg(mean + tid);
            par[512 + tid] = __ldg(beta + tid);
        } else if (tid < NCLS) {
            par[128 + tid] = __ldg(b2 + tid);
        }
    }
    __syncthreads();

    const int r0 = wr * 32 + (lane >> 2);
    const int cc = (lane & 3) * 2;
    const int n0 = wc * 32;

    // ---- GEMM1 ----
    float acc[2][4][4];
#pragma unroll
    for (int m = 0; m < 2; m++)
#pragma unroll
        for (int t = 0; t < 4; t++)
#pragma unroll
            for (int j = 0; j < 4; j++) acc[m][t][j] = 0.f;
    gemm_split(AHI, ALO, W1HI, W1LO, r0, cc, n0, lane, acc, KPAD);
    __syncthreads();   // all A/W1 reads done before overwriting A with T

    // ---- epilogue1: T = relu(acc + b1) -> back into A slots ----
    if (!head) {
#pragma unroll
        for (int m = 0; m < 2; m++) {
            int rm = r0 + m * 16;
#pragma unroll
            for (int t = 0; t < 4; t++) {
                int c0 = n0 + t * 8 + cc;
                float x0 = fmaxf(acc[m][t][0] + par[c0], 0.f);
                float x1 = fmaxf(acc[m][t][1] + par[c0 + 1], 0.f);
                float x2 = fmaxf(acc[m][t][2] + par[c0], 0.f);
                float x3 = fmaxf(acc[m][t][3] + par[c0 + 1], 0.f);
                uint32_t h, l;
                split2(x0, x1, h, l);
                sts32(AHI + a_off(rm, c0), h);
                sts32(ALO + a_off(rm, c0), l);
                split2(x2, x3, h, l);
                sts32(AHI + a_off(rm + 8, c0), h);
                sts32(ALO + a_off(rm + 8, c0), l);
            }
        }
    } else {
        float* Tf = (float*)(smem + SM_AHI);   // fp32, stride 132
#pragma unroll
        for (int m = 0; m < 2; m++) {
            int rm = r0 + m * 16;
#pragma unroll
            for (int t = 0; t < 4; t++) {
                int c0 = n0 + t * 8 + cc;
                Tf[rm * 132 + c0]           = fmaxf(acc[m][t][0] + par[c0], 0.f);
                Tf[rm * 132 + c0 + 1]       = fmaxf(acc[m][t][1] + par[c0 + 1], 0.f);
                Tf[(rm + 8) * 132 + c0]     = fmaxf(acc[m][t][2] + par[c0], 0.f);
                Tf[(rm + 8) * 132 + c0 + 1] = fmaxf(acc[m][t][3] + par[c0 + 1], 0.f);
            }
        }
    }
    __syncthreads();

    if (head) {
        // ---- fc2 SIMT: out[128x6] = T @ W2 + b2 ----
        if (tid < 128) {
            const float* Tf = (const float*)(smem + SM_AHI);
            const float* Wf = (const float*)(smem + SM_W2HI);
            float a6[NCLS];
#pragma unroll
            for (int c = 0; c < NCLS; c++) a6[c] = par[128 + c];
            for (int kk = 0; kk < D; kk++) {
                int k = (kk + lane) & (D - 1);
                float tv = Tf[tid * 132 + k];
#pragma unroll
                for (int c = 0; c < NCLS; c++) a6[c] += tv * Wf[k * NCLS + c];
            }
            if (row0 + tid < NN)
#pragma unroll
                for (int c = 0; c < NCLS; c++) out[(size_t)(row0 + tid) * NCLS + c] = a6[c];
        }
        return;
    }

    // ---- GEMM2 ----
#pragma unroll
    for (int m = 0; m < 2; m++)
#pragma unroll
        for (int t = 0; t < 4; t++)
#pragma unroll
            for (int j = 0; j < 4; j++) acc[m][t][j] = 0.f;
    gemm_split(AHI, ALO, W2HI, W2LO, r0, cc, n0, lane, acc, 128);

    // ---- epilogue2: BN(relu(acc + b2)) -> gmem fp32 + fp16 copy ----
#pragma unroll
    for (int m = 0; m < 2; m++) {
        int g0 = row0 + r0 + m * 16, g1 = g0 + 8;
#pragma unroll
        for (int t = 0; t < 4; t++) {
            int c0 = n0 + t * 8 + cc;
            float b0v = par[128 + c0], b1v = par[128 + c0 + 1];
            float s0 = par[256 + c0],  s1 = par[256 + c0 + 1];
            float m0 = par[384 + c0],  m1 = par[384 + c0 + 1];
            float t0 = par[512 + c0],  t1 = par[512 + c0 + 1];
            if (g0 < NN) {
                float v0 = (fmaxf(acc[m][t][0] + b0v, 0.f) - m0) * s0 + t0;
                float v1 = (fmaxf(acc[m][t][1] + b1v, 0.f) - m1) * s1 + t1;
                *reinterpret_cast<float2*>(out + (size_t)g0 * D + c0) = make_float2(v0, v1);
                *reinterpret_cast<__half2*>(out16 + (size_t)g0 * D + c0) =
                    __floats2half2_rn(v0, v1);
            }
            if (g1 < NN) {
                float v2 = (fmaxf(acc[m][t][2] + b0v, 0.f) - m0) * s0 + t0;
                float v3 = (fmaxf(acc[m][t][3] + b1v, 0.f) - m1) * s1 + t1;
                *reinterpret_cast<float2*>(out + (size_t)g1 * D + c0) = make_float2(v2, v3);
                *reinterpret_cast<__half2*>(out16 + (size_t)g1 * D + c0) =
                    __floats2half2_rn(v2, v3);
            }
        }
    }
}

// ---------------- launch ----------------------------------------------------
extern "C" void kernel_launch(void* const* d_in, const int* in_sizes, int n_in,
                              void* d_out, int out_size) {
    const float* x      = (const float*)d_in[0];
    const void*  ei     = (const void*)d_in[1];
    const float* w1_0   = (const float*)d_in[2];
    const float* b1_0   = (const float*)d_in[3];
    const float* w2_0   = (const float*)d_in[4];
    const float* b2_0   = (const float*)d_in[5];
    const float* ws1    = (const float*)d_in[6];
    const float* bs1    = (const float*)d_in[7];
    const float* ws2    = (const float*)d_in[8];
    const float* bs2    = (const float*)d_in[9];
    const float* gammas = (const float*)d_in[10];
    const float* betas  = (const float*)d_in[11];
    const float* means  = (const float*)d_in[12];
    const float* vars   = (const float*)d_in[13];
    const float* fc1_w  = (const float*)d_in[14];
    const float* fc1_b  = (const float*)d_in[15];
    const float* fc2_w  = (const float*)d_in[16];
    const float* fc2_b  = (const float*)d_in[17];
    float* out = (float*)d_out;

    float *agg12, *hA, *hB;
    __half *h16A, *h16B;
    cudaGetSymbolAddress((void**)&agg12, g_agg12);
    cudaGetSymbolAddress((void**)&hA, g_hA);
    cudaGetSymbolAddress((void**)&hB, g_hB);
    cudaGetSymbolAddress((void**)&h16A, g_h16A);
    cudaGetSymbolAddress((void**)&h16B, g_h16B);

    cudaFuncSetAttribute(mlp_mma<12, 16>, cudaFuncAttributeMaxDynamicSharedMemorySize, SM_TOTAL);
    cudaFuncSetAttribute(mlp_mma<128, 128>, cudaFuncAttributeMaxDynamicSharedMemorySize, SM_TOTAL);

    const int TC_GRID = (NN + 127) / 128;             // 391
    const int WARP_GRID = (NN * 32 + 255) / 256;      // one warp per node

    // ---- CSR build (4 launches) ----
    detect_zero_kernel<<<(NN + 255) / 256, 256>>>(ei);
    hist_kernel<<<(NE + 255) / 256, 256>>>(ei);
    scan_lookback_kernel<<<NBLK, 1024>>>();
    fill_kernel<<<(NE + 255) / 256, 256>>>(ei);

    // ---- layer 1 (nfeat=12): gather + MLP -> hA/h16A ----
    gather12_kernel<<<WARP_GRID, 256>>>(x);
    mlp_mma<12, 16><<<TC_GRID, 512, SM_TOTAL>>>(agg12, nullptr, w1_0, b1_0, w2_0, b2_0,
                                                gammas, betas, means, vars, hA, h16A, 0);

    // ---- layers 2-5: fused gather+MLP, ping-pong A<->B ----
    for (int i = 0; i < 4; i++) {
        const float*  hin   = (i & 1) ? hB   : hA;
        const __half* h16in = (i & 1) ? h16B : h16A;
        float*  hout   = (i & 1) ? hA   : hB;
        __half* h16out = (i & 1) ? h16A : h16B;
        mlp_mma<128, 128><<<TC_GRID, 512, SM_TOTAL>>>(hin, h16in,
                                                      ws1 + (size_t)i * D * D, bs1 + i * D,
                                                      ws2 + (size_t)i * D * D, bs2 + i * D,
                                                      gammas + (i + 1) * D, betas + (i + 1) * D,
                                                      means + (i + 1) * D, vars + (i + 1) * D,
                                                      hout, h16out, 0);
    }

    // ---- head: fc1 (mma) + fc2 (SIMT); final h is hA (after 4 flips) ----
    mlp_mma<128, 128><<<TC_GRID, 512, SM_TOTAL>>>(hA, nullptr, fc1_w, fc1_b, fc2_w, fc2_b,
                                                  nullptr, nullptr, nullptr, nullptr,
                                                  out, nullptr, 1);
}

// round 13
// speedup vs baseline: 1.1716x; 1.1716x over previous
#include <cuda_runtime.h>
#include <cuda_bf16.h>
#include <cuda_fp16.h>
#include <cstdint>

#define NN   50000
#define NE   1600000
#define D    128
#define NCLS 6
#define NBLK 49          // ceil(NN / 1024) scan blocks

// ---------------- scratch (static device globals; no runtime allocation) ----
__device__ float  g_agg12[NN * 12];
__device__ float  g_hA[(size_t)NN * D];
__device__ float  g_hB[(size_t)NN * D];
__device__ __half g_h16A[(size_t)NN * D];
__device__ __half g_h16B[(size_t)NN * D];
__device__ float  g_agg[(size_t)NN * D];
__device__ int    g_counts[NN];
__device__ int    g_rowptr[NN + 1];
__device__ int    g_cursor[NN];
__device__ int    g_col[NE];
__device__ volatile int g_scan_val[64];
__device__ volatile int g_scan_flag[64];
__device__ int    g_is64;   // 1 if edge_index really is int64, 0 if int32

// ---------------- small helpers ---------------------------------------------
__device__ __forceinline__ uint32_t smem_to_u32(const void* p) {
    uint32_t a;
    asm("{ .reg .u64 t; cvta.to.shared.u64 t, %1; cvt.u32.u64 %0, t; }"
        : "=r"(a) : "l"(p));
    return a;
}
__device__ __forceinline__ uint32_t lds32(uint32_t addr) {
    uint32_t v;
    asm volatile("ld.shared.b32 %0, [%1];" : "=r"(v) : "r"(addr));
    return v;
}
__device__ __forceinline__ void sts32(uint32_t addr, uint32_t v) {
    asm volatile("st.shared.b32 [%0], %1;" :: "r"(addr), "r"(v) : "memory");
}
// split two fp32 into bf16 hi/lo packed pairs
__device__ __forceinline__ void split2(float x, float y, uint32_t& hi, uint32_t& lo) {
    __nv_bfloat16 xh = __float2bfloat16(x), yh = __float2bfloat16(y);
    float xr = x - __bfloat162float(xh);
    float yr = y - __bfloat162float(yh);
    __nv_bfloat16 xl = __float2bfloat16(xr), yl = __float2bfloat16(yr);
    hi = ((uint32_t)__bfloat16_as_ushort(yh) << 16) | __bfloat16_as_ushort(xh);
    lo = ((uint32_t)__bfloat16_as_ushort(yl) << 16) | __bfloat16_as_ushort(xl);
}
__device__ __forceinline__ void mma16816(float* c, const uint32_t* a, const uint32_t* b) {
    asm volatile(
        "mma.sync.aligned.m16n8k16.row.col.f32.bf16.bf16.f32 "
        "{%0,%1,%2,%3},{%4,%5,%6,%7},{%8,%9},{%0,%1,%2,%3};"
        : "+f"(c[0]), "+f"(c[1]), "+f"(c[2]), "+f"(c[3])
        : "r"(a[0]), "r"(a[1]), "r"(a[2]), "r"(a[3]), "r"(b[0]), "r"(b[1]));
}
__device__ __forceinline__ void acc_h2(float4& a, uint2 p) {
    __half2 h0 = *reinterpret_cast<__half2*>(&p.x);
    __half2 h1 = *reinterpret_cast<__half2*>(&p.y);
    float2 f0 = __half22float2(h0);
    float2 f1 = __half22float2(h1);
    a.x += f0.x; a.y += f0.y; a.z += f1.x; a.w += f1.y;
}

// ---------------- smem tile layouts ------------------------------------------
#define KS 136                       // bf16 elems per row (padded)
__device__ __forceinline__ uint32_t a_off(int r, int k) {
    return (uint32_t)(r * KS + k) * 2;
}
// W tile: [n][k] with XOR swizzle on k bits 1..2 keyed by (n>>3)&3.
__device__ __forceinline__ uint32_t wt_off(int n, int k) {
    return (uint32_t)(n * KS + (k ^ ((((unsigned)n >> 3) & 3) << 1))) * 2;
}

#define SM_AHI   0
#define SM_ALO   34816
#define SM_W1HI  69632
#define SM_W1LO  104448
#define SM_W2HI  139264
#define SM_W2LO  174080
#define SM_PAR   208896              // 640 floats: b1|b2|sc|mn|bt
#define SM_TOTAL 211456

// ---------------- edge dtype detect + zero counts + reset scan flags --------
__global__ void detect_zero_kernel(const void* ei) {
    int i = blockIdx.x * blockDim.x + threadIdx.x;
    if (i < NN) g_counts[i] = 0;
    if (i < 64) { g_scan_flag[i] = 0; g_scan_val[i] = 0; }
    if (i == 0) {
        const long long* p = (const long long*)ei;
        int ok = 1;
        for (int j = 0; j < 64; j++) {
            long long v = p[j];
            if (v < 0 || v >= NN) { ok = 0; break; }
        }
        g_is64 = ok;
    }
}
__device__ __forceinline__ int edge_idx(const void* ei, long long pos, int is64) {
    if (is64) return (int)((const long long*)ei)[pos];
    return ((const int*)ei)[pos];
}

// ---------------- CSR build --------------------------------------------------
__global__ void hist_kernel(const void* __restrict__ ei) {
    int e = blockIdx.x * blockDim.x + threadIdx.x;
    if (e >= NE) return;
    const int is64 = g_is64;
    int dst = edge_idx(ei, (long long)NE + e, is64);
    if ((unsigned)dst < NN) atomicAdd(&g_counts[dst], 1);
}

// single-kernel exclusive scan with decoupled lookback (49 blocks co-resident)
__global__ void scan_lookback_kernel() {
    __shared__ int sh[1024];
    __shared__ int prefix_s;
    int b = blockIdx.x;
    int i = b * 1024 + threadIdx.x;
    int v = (i < NN) ? g_counts[i] : 0;
    sh[threadIdx.x] = v;
    __syncthreads();
#pragma unroll
    for (int off = 1; off < 1024; off <<= 1) {
        int t = (threadIdx.x >= off) ? sh[threadIdx.x - off] : 0;
        __syncthreads();
        sh[threadIdx.x] += t;
        __syncthreads();
    }
    int total = sh[1023];
    if (threadIdx.x == 0) {
        g_scan_val[b] = total;
        __threadfence();
        g_scan_flag[b] = 1;
        int pre = 0;
        for (int p = b - 1; p >= 0; p--) {
            while (g_scan_flag[p] == 0) {}
            pre += g_scan_val[p];
        }
        prefix_s = pre;
        if (b == NBLK - 1) g_rowptr[NN] = pre + total;
    }
    __syncthreads();
    if (i < NN) {
        int excl = prefix_s + sh[threadIdx.x] - v;
        g_rowptr[i] = excl;
        g_cursor[i] = excl;
    }
}

__global__ void fill_kernel(const void* __restrict__ ei) {
    int e = blockIdx.x * blockDim.x + threadIdx.x;
    if (e >= NE) return;
    const int is64 = g_is64;
    int src = edge_idx(ei, e, is64);
    int dst = edge_idx(ei, (long long)NE + e, is64);
    if ((unsigned)src >= NN || (unsigned)dst >= NN) return;
    int pos = atomicAdd(&g_cursor[dst], 1);
    g_col[pos] = src;
}

// ---------------- CSR gathers ------------------------------------------------
__global__ void gather12_kernel(const float* __restrict__ x) {
    int n = (blockIdx.x * blockDim.x + threadIdx.x) >> 5;
    if (n >= NN) return;
    int lane = threadIdx.x & 31;
    int beg = g_rowptr[n], end = g_rowptr[n + 1];
    float acc = (lane < 12) ? x[(size_t)n * 12 + lane] : 0.f;
    for (int e = beg; e < end; e++) {
        int s = g_col[e];
        if (lane < 12) acc += x[(size_t)s * 12 + lane];
    }
    if (lane < 12) g_agg12[(size_t)n * 12 + lane] = acc;
}
// fp16 neighbor gather: agg[n] = h_fp32[n] + sum h16[src].  One warp/node,
// lane owns 4 features (8B per row), 4 edges in flight.
__global__ void gather128_h16_kernel(const __half* __restrict__ h16,
                                     const float* __restrict__ h,
                                     float* __restrict__ agg) {
    int n = (blockIdx.x * blockDim.x + threadIdx.x) >> 5;
    if (n >= NN) return;
    int lane = threadIdx.x & 31;
    int beg = g_rowptr[n], end = g_rowptr[n + 1];
    const int fo = lane * 4;
    float4 acc = *reinterpret_cast<const float4*>(h + (size_t)n * D + fo);
    float4 acc2 = make_float4(0.f, 0.f, 0.f, 0.f);
    int e = beg;
    for (; e + 3 < end; e += 4) {
        int s0 = g_col[e], s1 = g_col[e + 1], s2 = g_col[e + 2], s3 = g_col[e + 3];
        uint2 p0 = *reinterpret_cast<const uint2*>(h16 + (size_t)s0 * D + fo);
        uint2 p1 = *reinterpret_cast<const uint2*>(h16 + (size_t)s1 * D + fo);
        uint2 p2 = *reinterpret_cast<const uint2*>(h16 + (size_t)s2 * D + fo);
        uint2 p3 = *reinterpret_cast<const uint2*>(h16 + (size_t)s3 * D + fo);
        acc_h2(acc, p0);  acc_h2(acc2, p1);
        acc_h2(acc, p2);  acc_h2(acc2, p3);
    }
    for (; e < end; e++) {
        uint2 p = *reinterpret_cast<const uint2*>(h16 + (size_t)g_col[e] * D + fo);
        acc_h2(acc, p);
    }
    acc.x += acc2.x; acc.y += acc2.y; acc.z += acc2.z; acc.w += acc2.w;
    *reinterpret_cast<float4*>(agg + (size_t)n * D + fo) = acc;
}

// ============================================================================
// mma.sync fused MLP: 128-row tile per CTA, 512 threads (16 warps, 4x4 grid).
// Warp (wr, wc): rows [32wr,+32) as 2 m16 tiles, cols [32wc,+32) as 4 n8 tiles.
// bf16 hi/lo split, 3 passes, fp32 accum.
// head==0: out = BN(relu(relu(A@W1+b1)@W2+b2)), + fp16 copy to out16.
// head==1: fc1 (mma) + fc2 (SIMT).
// ============================================================================
__device__ __forceinline__ void gemm_split(
    uint32_t aHi, uint32_t aLo, uint32_t wHi, uint32_t wLo,
    int r0, int cc, int n0, int lane, float acc[2][4][4], int kpad) {
#pragma unroll 2
    for (int kb = 0; kb < kpad; kb += 16) {
        uint32_t ah[2][4], al[2][4];
#pragma unroll
        for (int m = 0; m < 2; m++) {
            int rm = r0 + m * 16;
            ah[m][0] = lds32(aHi + a_off(rm,     kb + cc));
            ah[m][1] = lds32(aHi + a_off(rm + 8, kb + cc));
            ah[m][2] = lds32(aHi + a_off(rm,     kb + cc + 8));
            ah[m][3] = lds32(aHi + a_off(rm + 8, kb + cc + 8));
            al[m][0] = lds32(aLo + a_off(rm,     kb + cc));
            al[m][1] = lds32(aLo + a_off(rm + 8, kb + cc));
            al[m][2] = lds32(aLo + a_off(rm,     kb + cc + 8));
            al[m][3] = lds32(aLo + a_off(rm + 8, kb + cc + 8));
        }
#pragma unroll
        for (int t = 0; t < 4; t++) {
            int nl = n0 + t * 8 + (lane >> 2);
            uint32_t bh[2], bl[2];
            bh[0] = lds32(wHi + wt_off(nl, kb + cc));
            bh[1] = lds32(wHi + wt_off(nl, kb + cc + 8));
            bl[0] = lds32(wLo + wt_off(nl, kb + cc));
            bl[1] = lds32(wLo + wt_off(nl, kb + cc + 8));
            mma16816(acc[0][t], ah[0], bh);
            mma16816(acc[1][t], ah[1], bh);
            mma16816(acc[0][t], al[0], bh);
            mma16816(acc[1][t], al[1], bh);
            mma16816(acc[0][t], ah[0], bl);
            mma16816(acc[1][t], ah[1], bl);
        }
    }
}

template <int KIN, int KPAD>
__global__ __launch_bounds__(512, 1) void mlp_mma(
    const float* __restrict__ A,
    const float* __restrict__ W1, const float* __restrict__ b1,
    const float* __restrict__ W2, const float* __restrict__ b2,
    const float* __restrict__ gamma, const float* __restrict__ beta,
    const float* __restrict__ mean, const float* __restrict__ var,
    float* __restrict__ out, __half* __restrict__ out16, int head) {
    extern __shared__ char smem[];
    const uint32_t sb = smem_to_u32(smem);
    const int tid = threadIdx.x;
    const int lane = tid & 31;
    const int wid = tid >> 5;
    const int wr = wid >> 2, wc = wid & 3;    // 4 x 4 warps
    const int row0 = blockIdx.x * 128;

    const uint32_t AHI = sb + SM_AHI, ALO = sb + SM_ALO;
    const uint32_t W1HI = sb + SM_W1HI, W1LO = sb + SM_W1LO;
    const uint32_t W2HI = sb + SM_W2HI, W2LO = sb + SM_W2LO;
    float* par = (float*)(smem + SM_PAR);   // b1[128] b2[128] sc[128] mn[128] bt[128]

    // ---- stage A [row][k] hi/lo ----
    {
        int r = tid >> 2, q = tid & 3;
        int gr = row0 + r;
        const float* ar = A + (size_t)gr * KIN;
        bool ok = gr < NN;
#pragma unroll
        for (int j = 0; j < KPAD / 16; j++) {
            int k = q * (KPAD / 4) + j * 4;
            float4 v = make_float4(0.f, 0.f, 0.f, 0.f);
            if (ok) {
                if (k + 3 < KIN) v = *reinterpret_cast<const float4*>(ar + k);
                else {
                    if (k     < KIN) v.x = ar[k];
                    if (k + 1 < KIN) v.y = ar[k + 1];
                    if (k + 2 < KIN) v.z = ar[k + 2];
                    if (k + 3 < KIN) v.w = ar[k + 3];
                }
            }
            uint32_t h0, l0, h1, l1;
            split2(v.x, v.y, h0, l0);
            split2(v.z, v.w, h1, l1);
            sts32(AHI + a_off(r, k),     h0);
            sts32(AHI + a_off(r, k + 2), h1);
            sts32(ALO + a_off(r, k),     l0);
            sts32(ALO + a_off(r, k + 2), l1);
        }
    }
    // ---- stage W1 transposed [n][k] hi/lo (coalesced gmem reads) ----
    {
        int n = tid & 127;
        int ko = (tid >> 7) * 2;   // 0,2,4,6
        for (int kk = 0; kk < KPAD; kk += 8) {
            int k = kk + ko;
            float v0 = (k     < KIN) ? __ldg(W1 + (size_t)k * D + n) : 0.f;
            float v1 = (k + 1 < KIN) ? __ldg(W1 + (size_t)(k + 1) * D + n) : 0.f;
            uint32_t hi, lo;
            split2(v0, v1, hi, lo);
            sts32(W1HI + wt_off(n, k), hi);
            sts32(W1LO + wt_off(n, k), lo);
        }
    }
    // ---- stage W2 ----
    if (!head) {
        int n = tid & 127;
        int ko = (tid >> 7) * 2;
        for (int kk = 0; kk < 128; kk += 8) {
            int k = kk + ko;
            float v0 = __ldg(W2 + (size_t)k * D + n);
            float v1 = __ldg(W2 + (size_t)(k + 1) * D + n);
            uint32_t hi, lo;
            split2(v0, v1, hi, lo);
            sts32(W2HI + wt_off(n, k), hi);
            sts32(W2LO + wt_off(n, k), lo);
        }
    } else {
        float* w2f = (float*)(smem + SM_W2HI);
        for (int i = tid; i < D * NCLS; i += 512) w2f[i] = __ldg(W2 + i);
    }
    // ---- stage params ----
    if (tid < 128) {
        par[tid] = __ldg(b1 + tid);
        if (!head) {
            par[128 + tid] = __ldg(b2 + tid);
            par[256 + tid] = __ldg(gamma + tid) * rsqrtf(__ldg(var + tid) + 1e-5f);
            par[384 + tid] = __ldg(mean + tid);
            par[512 + tid] = __ldg(beta + tid);
        } else if (tid < NCLS) {
            par[128 + tid] = __ldg(b2 + tid);
        }
    }
    __syncthreads();

    const int r0 = wr * 32 + (lane >> 2);
    const int cc = (lane & 3) * 2;
    const int n0 = wc * 32;

    // ---- GEMM1 ----
    float acc[2][4][4];
#pragma unroll
    for (int m = 0; m < 2; m++)
#pragma unroll
        for (int t = 0; t < 4; t++)
#pragma unroll
            for (int j = 0; j < 4; j++) acc[m][t][j] = 0.f;
    gemm_split(AHI, ALO, W1HI, W1LO, r0, cc, n0, lane, acc, KPAD);
    __syncthreads();   // all A/W1 reads done before overwriting A with T

    // ---- epilogue1: T = relu(acc + b1) -> back into A slots ----
    if (!head) {
#pragma unroll
        for (int m = 0; m < 2; m++) {
            int rm = r0 + m * 16;
#pragma unroll
            for (int t = 0; t < 4; t++) {
                int c0 = n0 + t * 8 + cc;
                float x0 = fmaxf(acc[m][t][0] + par[c0], 0.f);
                float x1 = fmaxf(acc[m][t][1] + par[c0 + 1], 0.f);
                float x2 = fmaxf(acc[m][t][2] + par[c0], 0.f);
                float x3 = fmaxf(acc[m][t][3] + par[c0 + 1], 0.f);
                uint32_t h, l;
                split2(x0, x1, h, l);
                sts32(AHI + a_off(rm, c0), h);
                sts32(ALO + a_off(rm, c0), l);
                split2(x2, x3, h, l);
                sts32(AHI + a_off(rm + 8, c0), h);
                sts32(ALO + a_off(rm + 8, c0), l);
            }
        }
    } else {
        float* Tf = (float*)(smem + SM_AHI);   // fp32, stride 132
#pragma unroll
        for (int m = 0; m < 2; m++) {
            int rm = r0 + m * 16;
#pragma unroll
            for (int t = 0; t < 4; t++) {
                int c0 = n0 + t * 8 + cc;
                Tf[rm * 132 + c0]           = fmaxf(acc[m][t][0] + par[c0], 0.f);
                Tf[rm * 132 + c0 + 1]       = fmaxf(acc[m][t][1] + par[c0 + 1], 0.f);
                Tf[(rm + 8) * 132 + c0]     = fmaxf(acc[m][t][2] + par[c0], 0.f);
                Tf[(rm + 8) * 132 + c0 + 1] = fmaxf(acc[m][t][3] + par[c0 + 1], 0.f);
            }
        }
    }
    __syncthreads();

    if (head) {
        // ---- fc2 SIMT: out[128x6] = T @ W2 + b2 ----
        if (tid < 128) {
            const float* Tf = (const float*)(smem + SM_AHI);
            const float* Wf = (const float*)(smem + SM_W2HI);
            float a6[NCLS];
#pragma unroll
            for (int c = 0; c < NCLS; c++) a6[c] = par[128 + c];
            for (int kk = 0; kk < D; kk++) {
                int k = (kk + lane) & (D - 1);
                float tv = Tf[tid * 132 + k];
#pragma unroll
                for (int c = 0; c < NCLS; c++) a6[c] += tv * Wf[k * NCLS + c];
            }
            if (row0 + tid < NN)
#pragma unroll
                for (int c = 0; c < NCLS; c++) out[(size_t)(row0 + tid) * NCLS + c] = a6[c];
        }
        return;
    }

    // ---- GEMM2 ----
#pragma unroll
    for (int m = 0; m < 2; m++)
#pragma unroll
        for (int t = 0; t < 4; t++)
#pragma unroll
            for (int j = 0; j < 4; j++) acc[m][t][j] = 0.f;
    gemm_split(AHI, ALO, W2HI, W2LO, r0, cc, n0, lane, acc, 128);

    // ---- epilogue2: BN(relu(acc + b2)) -> gmem fp32 + fp16 copy ----
#pragma unroll
    for (int m = 0; m < 2; m++) {
        int g0 = row0 + r0 + m * 16, g1 = g0 + 8;
#pragma unroll
        for (int t = 0; t < 4; t++) {
            int c0 = n0 + t * 8 + cc;
            float b0v = par[128 + c0], b1v = par[128 + c0 + 1];
            float s0 = par[256 + c0],  s1 = par[256 + c0 + 1];
            float m0 = par[384 + c0],  m1 = par[384 + c0 + 1];
            float t0 = par[512 + c0],  t1 = par[512 + c0 + 1];
            if (g0 < NN) {
                float v0 = (fmaxf(acc[m][t][0] + b0v, 0.f) - m0) * s0 + t0;
                float v1 = (fmaxf(acc[m][t][1] + b1v, 0.f) - m1) * s1 + t1;
                *reinterpret_cast<float2*>(out + (size_t)g0 * D + c0) = make_float2(v0, v1);
                *reinterpret_cast<__half2*>(out16 + (size_t)g0 * D + c0) =
                    __floats2half2_rn(v0, v1);
            }
            if (g1 < NN) {
                float v2 = (fmaxf(acc[m][t][2] + b0v, 0.f) - m0) * s0 + t0;
                float v3 = (fmaxf(acc[m][t][3] + b1v, 0.f) - m1) * s1 + t1;
                *reinterpret_cast<float2*>(out + (size_t)g1 * D + c0) = make_float2(v2, v3);
                *reinterpret_cast<__half2*>(out16 + (size_t)g1 * D + c0) =
                    __floats2half2_rn(v2, v3);
            }
        }
    }
}

// ---------------- launch ----------------------------------------------------
extern "C" void kernel_launch(void* const* d_in, const int* in_sizes, int n_in,
                              void* d_out, int out_size) {
    const float* x      = (const float*)d_in[0];
    const void*  ei     = (const void*)d_in[1];
    const float* w1_0   = (const float*)d_in[2];
    const float* b1_0   = (const float*)d_in[3];
    const float* w2_0   = (const float*)d_in[4];
    const float* b2_0   = (const float*)d_in[5];
    const float* ws1    = (const float*)d_in[6];
    const float* bs1    = (const float*)d_in[7];
    const float* ws2    = (const float*)d_in[8];
    const float* bs2    = (const float*)d_in[9];
    const float* gammas = (const float*)d_in[10];
    const float* betas  = (const float*)d_in[11];
    const float* means  = (const float*)d_in[12];
    const float* vars   = (const float*)d_in[13];
    const float* fc1_w  = (const float*)d_in[14];
    const float* fc1_b  = (const float*)d_in[15];
    const float* fc2_w  = (const float*)d_in[16];
    const float* fc2_b  = (const float*)d_in[17];
    float* out = (float*)d_out;

    float *agg12, *hA, *hB, *agg;
    __half *h16A, *h16B;
    cudaGetSymbolAddress((void**)&agg12, g_agg12);
    cudaGetSymbolAddress((void**)&hA, g_hA);
    cudaGetSymbolAddress((void**)&hB, g_hB);
    cudaGetSymbolAddress((void**)&h16A, g_h16A);
    cudaGetSymbolAddress((void**)&h16B, g_h16B);
    cudaGetSymbolAddress((void**)&agg, g_agg);

    cudaFuncSetAttribute(mlp_mma<12, 16>, cudaFuncAttributeMaxDynamicSharedMemorySize, SM_TOTAL);
    cudaFuncSetAttribute(mlp_mma<128, 128>, cudaFuncAttributeMaxDynamicSharedMemorySize, SM_TOTAL);

    const int TC_GRID = (NN + 127) / 128;             // 391
    const int WARP_GRID = (NN * 32 + 255) / 256;      // one warp per node

    // ---- CSR build (4 launches) ----
    detect_zero_kernel<<<(NN + 255) / 256, 256>>>(ei);
    hist_kernel<<<(NE + 255) / 256, 256>>>(ei);
    scan_lookback_kernel<<<NBLK, 1024>>>();
    fill_kernel<<<(NE + 255) / 256, 256>>>(ei);

    // ---- layer 1 (nfeat=12): gather + MLP -> hA/h16A ----
    gather12_kernel<<<WARP_GRID, 256>>>(x);
    mlp_mma<12, 16><<<TC_GRID, 512, SM_TOTAL>>>(agg12, w1_0, b1_0, w2_0, b2_0,
                                                gammas, betas, means, vars, hA, h16A, 0);

    // ---- layers 2-5: standalone gather (high occupancy), ping-pong h ----
    for (int i = 0; i < 4; i++) {
        const float*  hin   = (i & 1) ? hB   : hA;
        const __half* h16in = (i & 1) ? h16B : h16A;
        float*  hout   = (i & 1) ? hA   : hB;
        __half* h16out = (i & 1) ? h16A : h16B;
        gather128_h16_kernel<<<WARP_GRID, 256>>>(h16in, hin, agg);
        mlp_mma<128, 128><<<TC_GRID, 512, SM_TOTAL>>>(agg,
                                                      ws1 + (size_t)i * D * D, bs1 + i * D,
                                                      ws2 + (size_t)i * D * D, bs2 + i * D,
                                                      gammas + (i + 1) * D, betas + (i + 1) * D,
                                                      means + (i + 1) * D, vars + (i + 1) * D,
                                                      hout, h16out, 0);
    }

    // ---- head: fc1 (mma) + fc2 (SIMT); final h is hA (after 4 flips) ----
    mlp_mma<128, 128><<<TC_GRID, 512, SM_TOTAL>>>(hA, fc1_w, fc1_b, fc2_w, fc2_b,
                                                  nullptr, nullptr, nullptr, nullptr,
                                                  out, nullptr, 1);
}

// round 15
// speedup vs baseline: 1.2821x; 1.0943x over previous
#include <cuda_runtime.h>
#include <cuda_bf16.h>
#include <cuda_fp16.h>
#include <cstdint>

#define NN   50000
#define NE   1600000
#define D    128
#define NCLS 6
#define NBLK 49          // ceil(NN / 1024) scan blocks
#define NTILES 11        // pre-split weight tiles
#define TILE_WORDS 8704  // 34816 B / 4

// ---------------- scratch (static device globals; no runtime allocation) ----
__device__ float  g_agg12[NN * 12];
__device__ float  g_hA[(size_t)NN * D];
__device__ float  g_hB[(size_t)NN * D];
__device__ __half g_h16A[(size_t)NN * D];
__device__ __half g_h16B[(size_t)NN * D];
__device__ float  g_agg[(size_t)NN * D];
__device__ int    g_counts[NN];
__device__ int    g_rowptr[NN + 1];
__device__ int    g_cursor[NN];
__device__ int    g_col[NE];
__device__ volatile int g_scan_val[64];
__device__ volatile int g_scan_flag[64];
__device__ int    g_is64;
// pre-split weight tile images: [tile][hi/lo][words]
__device__ uint32_t g_wt[NTILES][2][TILE_WORDS];

// ---------------- small helpers ---------------------------------------------
__device__ __forceinline__ uint32_t smem_to_u32(const void* p) {
    uint32_t a;
    asm("{ .reg .u64 t; cvta.to.shared.u64 t, %1; cvt.u32.u64 %0, t; }"
        : "=r"(a) : "l"(p));
    return a;
}
__device__ __forceinline__ uint32_t lds32(uint32_t addr) {
    uint32_t v;
    asm volatile("ld.shared.b32 %0, [%1];" : "=r"(v) : "r"(addr));
    return v;
}
__device__ __forceinline__ void sts32(uint32_t addr, uint32_t v) {
    asm volatile("st.shared.b32 [%0], %1;" :: "r"(addr), "r"(v) : "memory");
}
#define CP_ASYNC16(smem, gptr) \
    asm volatile("cp.async.cg.shared.global [%0], [%1], 16;" \
                 :: "r"(smem), "l"(gptr) : "memory")
#define CP_COMMIT() asm volatile("cp.async.commit_group;" ::: "memory")
#define CP_WAIT(n)  asm volatile("cp.async.wait_group %0;" :: "n"(n) : "memory")

// split two fp32 into bf16 hi/lo packed pairs
__device__ __forceinline__ void split2(float x, float y, uint32_t& hi, uint32_t& lo) {
    __nv_bfloat16 xh = __float2bfloat16(x), yh = __float2bfloat16(y);
    float xr = x - __bfloat162float(xh);
    float yr = y - __bfloat162float(yh);
    __nv_bfloat16 xl = __float2bfloat16(xr), yl = __float2bfloat16(yr);
    hi = ((uint32_t)__bfloat16_as_ushort(yh) << 16) | __bfloat16_as_ushort(xh);
    lo = ((uint32_t)__bfloat16_as_ushort(yl) << 16) | __bfloat16_as_ushort(xl);
}
__device__ __forceinline__ void mma16816(float* c, const uint32_t* a, const uint32_t* b) {
    asm volatile(
        "mma.sync.aligned.m16n8k16.row.col.f32.bf16.bf16.f32 "
        "{%0,%1,%2,%3},{%4,%5,%6,%7},{%8,%9},{%0,%1,%2,%3};"
        : "+f"(c[0]), "+f"(c[1]), "+f"(c[2]), "+f"(c[3])
        : "r"(a[0]), "r"(a[1]), "r"(a[2]), "r"(a[3]), "r"(b[0]), "r"(b[1]));
}
__device__ __forceinline__ void acc_h2(float4& a, uint2 p) {
    __half2 h0 = *reinterpret_cast<__half2*>(&p.x);
    __half2 h1 = *reinterpret_cast<__half2*>(&p.y);
    float2 f0 = __half22float2(h0);
    float2 f1 = __half22float2(h1);
    a.x += f0.x; a.y += f0.y; a.z += f1.x; a.w += f1.y;
}

// ---------------- smem tile layouts ------------------------------------------
#define KS 136                       // bf16 elems per row (padded)
__device__ __forceinline__ uint32_t a_off(int r, int k) {
    return (uint32_t)(r * KS + k) * 2;
}
// W tile: [n][k] with XOR swizzle on k bits 1..2 keyed by (n>>3)&3.
__device__ __forceinline__ uint32_t wt_off(int n, int k) {
    return (uint32_t)(n * KS + (k ^ ((((unsigned)n >> 3) & 3) << 1))) * 2;
}

#define SM_AHI   0
#define SM_ALO   34816
#define SM_W1HI  69632
#define SM_W1LO  104448
#define SM_W2HI  139264
#define SM_W2LO  174080
#define SM_PAR   208896              // 640 floats: b1|b2|sc|mn|bt
#define SM_TOTAL 211456

// ---------------- prep: pre-split weights into swizzled tile images ---------
// tiles: 0=lay1 W1(kin12), 1=lay1 W2, 2+2i=ws1[i], 3+2i=ws2[i], 10=fc1
__global__ void prep_weights_kernel(const float* __restrict__ w1_0,
                                    const float* __restrict__ w2_0,
                                    const float* __restrict__ ws1,
                                    const float* __restrict__ ws2,
                                    const float* __restrict__ fc1_w) {
    int idx = blockIdx.x * blockDim.x + threadIdx.x;
    if (idx >= NTILES * 128 * 68) return;
    int t = idx / (128 * 68);
    int rem = idx - t * (128 * 68);
    int n = rem / 68;
    int kp = rem - n * 68;
    int k = kp * 2;
    const float* W;
    int kin;
    if (t == 0)       { W = w1_0;  kin = 12; }
    else if (t == 1)  { W = w2_0;  kin = 128; }
    else if (t == 10) { W = fc1_w; kin = 128; }
    else {
        int i = (t - 2) >> 1;
        W = (((t - 2) & 1) == 0 ? ws1 : ws2) + (size_t)i * D * D;
        kin = 128;
    }
    float v0 = (k < kin)     ? __ldg(W + (size_t)k * D + n)       : 0.f;
    float v1 = (k + 1 < kin) ? __ldg(W + (size_t)(k + 1) * D + n) : 0.f;
    uint32_t hi, lo;
    split2(v0, v1, hi, lo);
    uint32_t off = wt_off(n, k) >> 2;
    g_wt[t][0][off] = hi;
    g_wt[t][1][off] = lo;
}

// ---------------- edge dtype detect + zero counts + reset scan flags --------
__global__ void detect_zero_kernel(const void* ei) {
    int i = blockIdx.x * blockDim.x + threadIdx.x;
    if (i < NN) g_counts[i] = 0;
    if (i < 64) { g_scan_flag[i] = 0; g_scan_val[i] = 0; }
    if (i == 0) {
        const long long* p = (const long long*)ei;
        int ok = 1;
        for (int j = 0; j < 64; j++) {
            long long v = p[j];
            if (v < 0 || v >= NN) { ok = 0; break; }
        }
        g_is64 = ok;
    }
}
__device__ __forceinline__ int edge_idx(const void* ei, long long pos, int is64) {
    if (is64) return (int)((const long long*)ei)[pos];
    return ((const int*)ei)[pos];
}

// ---------------- CSR build --------------------------------------------------
__global__ void hist_kernel(const void* __restrict__ ei) {
    int e = blockIdx.x * blockDim.x + threadIdx.x;
    if (e >= NE) return;
    const int is64 = g_is64;
    int dst = edge_idx(ei, (long long)NE + e, is64);
    if ((unsigned)dst < NN) atomicAdd(&g_counts[dst], 1);
}
__global__ void scan_lookback_kernel() {
    __shared__ int sh[1024];
    __shared__ int prefix_s;
    int b = blockIdx.x;
    int i = b * 1024 + threadIdx.x;
    int v = (i < NN) ? g_counts[i] : 0;
    sh[threadIdx.x] = v;
    __syncthreads();
#pragma unroll
    for (int off = 1; off < 1024; off <<= 1) {
        int t = (threadIdx.x >= off) ? sh[threadIdx.x - off] : 0;
        __syncthreads();
        sh[threadIdx.x] += t;
        __syncthreads();
    }
    int total = sh[1023];
    if (threadIdx.x == 0) {
        g_scan_val[b] = total;
        __threadfence();
        g_scan_flag[b] = 1;
        int pre = 0;
        for (int p = b - 1; p >= 0; p--) {
            while (g_scan_flag[p] == 0) {}
            pre += g_scan_val[p];
        }
        prefix_s = pre;
        if (b == NBLK - 1) g_rowptr[NN] = pre + total;
    }
    __syncthreads();
    if (i < NN) {
        int excl = prefix_s + sh[threadIdx.x] - v;
        g_rowptr[i] = excl;
        g_cursor[i] = excl;
    }
}
__global__ void fill_kernel(const void* __restrict__ ei) {
    int e = blockIdx.x * blockDim.x + threadIdx.x;
    if (e >= NE) return;
    const int is64 = g_is64;
    int src = edge_idx(ei, e, is64);
    int dst = edge_idx(ei, (long long)NE + e, is64);
    if ((unsigned)src >= NN || (unsigned)dst >= NN) return;
    int pos = atomicAdd(&g_cursor[dst], 1);
    g_col[pos] = src;
}

// ---------------- CSR gathers ------------------------------------------------
__global__ void gather12_kernel(const float* __restrict__ x) {
    int n = (blockIdx.x * blockDim.x + threadIdx.x) >> 5;
    if (n >= NN) return;
    int lane = threadIdx.x & 31;
    int beg = g_rowptr[n], end = g_rowptr[n + 1];
    float acc = (lane < 12) ? x[(size_t)n * 12 + lane] : 0.f;
    for (int e = beg; e < end; e++) {
        int s = g_col[e];
        if (lane < 12) acc += x[(size_t)s * 12 + lane];
    }
    if (lane < 12) g_agg12[(size_t)n * 12 + lane] = acc;
}
__global__ void gather128_h16_kernel(const __half* __restrict__ h16,
                                     const float* __restrict__ h,
                                     float* __restrict__ agg) {
    int n = (blockIdx.x * blockDim.x + threadIdx.x) >> 5;
    if (n >= NN) return;
    int lane = threadIdx.x & 31;
    int beg = g_rowptr[n], end = g_rowptr[n + 1];
    const int fo = lane * 4;
    float4 acc = *reinterpret_cast<const float4*>(h + (size_t)n * D + fo);
    float4 acc2 = make_float4(0.f, 0.f, 0.f, 0.f);
    int e = beg;
    for (; e + 3 < end; e += 4) {
        int s0 = g_col[e], s1 = g_col[e + 1], s2 = g_col[e + 2], s3 = g_col[e + 3];
        uint2 p0 = *reinterpret_cast<const uint2*>(h16 + (size_t)s0 * D + fo);
        uint2 p1 = *reinterpret_cast<const uint2*>(h16 + (size_t)s1 * D + fo);
        uint2 p2 = *reinterpret_cast<const uint2*>(h16 + (size_t)s2 * D + fo);
        uint2 p3 = *reinterpret_cast<const uint2*>(h16 + (size_t)s3 * D + fo);
        acc_h2(acc, p0);  acc_h2(acc2, p1);
        acc_h2(acc, p2);  acc_h2(acc2, p3);
    }
    for (; e < end; e++) {
        uint2 p = *reinterpret_cast<const uint2*>(h16 + (size_t)g_col[e] * D + fo);
        acc_h2(acc, p);
    }
    acc.x += acc2.x; acc.y += acc2.y; acc.z += acc2.z; acc.w += acc2.w;
    *reinterpret_cast<float4*>(agg + (size_t)n * D + fo) = acc;
}

// ============================================================================
// mma.sync fused MLP: 128-row tile per CTA, 512 threads (16 warps, 4x4 grid).
// W tiles arrive via cp.async from pre-split gmem images (group0=W1, group1=W2).
// bf16 hi/lo split, 3 passes, fp32 accum.
// head==0: out = BN(relu(relu(A@W1+b1)@W2+b2)), + fp16 copy to out16.
// head==1: fc1 (mma) + fc2 (SIMT, fp32 W2f).
// ============================================================================
__device__ __forceinline__ void gemm_split(
    uint32_t aHi, uint32_t aLo, uint32_t wHi, uint32_t wLo,
    int r0, int cc, int n0, int lane, float acc[2][4][4], int kpad) {
#pragma unroll 2
    for (int kb = 0; kb < kpad; kb += 16) {
        uint32_t ah[2][4], al[2][4];
#pragma unroll
        for (int m = 0; m < 2; m++) {
            int rm = r0 + m * 16;
            ah[m][0] = lds32(aHi + a_off(rm,     kb + cc));
            ah[m][1] = lds32(aHi + a_off(rm + 8, kb + cc));
            ah[m][2] = lds32(aHi + a_off(rm,     kb + cc + 8));
            ah[m][3] = lds32(aHi + a_off(rm + 8, kb + cc + 8));
            al[m][0] = lds32(aLo + a_off(rm,     kb + cc));
            al[m][1] = lds32(aLo + a_off(rm + 8, kb + cc));
            al[m][2] = lds32(aLo + a_off(rm,     kb + cc + 8));
            al[m][3] = lds32(aLo + a_off(rm + 8, kb + cc + 8));
        }
#pragma unroll
        for (int t = 0; t < 4; t++) {
            int nl = n0 + t * 8 + (lane >> 2);
            uint32_t bh[2], bl[2];
            bh[0] = lds32(wHi + wt_off(nl, kb + cc));
            bh[1] = lds32(wHi + wt_off(nl, kb + cc + 8));
            bl[0] = lds32(wLo + wt_off(nl, kb + cc));
            bl[1] = lds32(wLo + wt_off(nl, kb + cc + 8));
            mma16816(acc[0][t], ah[0], bh);
            mma16816(acc[1][t], ah[1], bh);
            mma16816(acc[0][t], al[0], bh);
            mma16816(acc[1][t], al[1], bh);
            mma16816(acc[0][t], ah[0], bl);
            mma16816(acc[1][t], ah[1], bl);
        }
    }
}

template <int KIN, int KPAD>
__global__ __launch_bounds__(512, 1) void mlp_mma(
    const float* __restrict__ A,
    const uint32_t* __restrict__ w1hi, const uint32_t* __restrict__ w1lo,
    const uint32_t* __restrict__ w2hi, const uint32_t* __restrict__ w2lo,
    const float* __restrict__ b1,
    const float* __restrict__ W2f, const float* __restrict__ b2,
    const float* __restrict__ gamma, const float* __restrict__ beta,
    const float* __restrict__ mean, const float* __restrict__ var,
    float* __restrict__ out, __half* __restrict__ out16, int head) {
    extern __shared__ char smem[];
    const uint32_t sb = smem_to_u32(smem);
    const int tid = threadIdx.x;
    const int lane = tid & 31;
    const int wid = tid >> 5;
    const int wr = wid >> 2, wc = wid & 3;    // 4 x 4 warps
    const int row0 = blockIdx.x * 128;

    const uint32_t AHI = sb + SM_AHI, ALO = sb + SM_ALO;
    const uint32_t W1HI = sb + SM_W1HI, W1LO = sb + SM_W1LO;
    const uint32_t W2HI = sb + SM_W2HI, W2LO = sb + SM_W2LO;
    float* par = (float*)(smem + SM_PAR);   // b1[128] b2[128] sc[128] mn[128] bt[128]

    // ---- issue async W tile copies FIRST (overlap with A staging) ----
    for (int i = tid; i < 2176; i += 512) {
        CP_ASYNC16(W1HI + i * 16, (const char*)w1hi + i * 16);
        CP_ASYNC16(W1LO + i * 16, (const char*)w1lo + i * 16);
    }
    CP_COMMIT();                              // group: W1
    if (!head) {
        for (int i = tid; i < 2176; i += 512) {
            CP_ASYNC16(W2HI + i * 16, (const char*)w2hi + i * 16);
            CP_ASYNC16(W2LO + i * 16, (const char*)w2lo + i * 16);
        }
    }
    CP_COMMIT();                              // group: W2 (possibly empty)

    // ---- stage A [row][k] hi/lo ----
    {
        int r = tid >> 2, q = tid & 3;
        int gr = row0 + r;
        const float* ar = A + (size_t)gr * KIN;
        bool ok = gr < NN;
#pragma unroll
        for (int j = 0; j < KPAD / 16; j++) {
            int k = q * (KPAD / 4) + j * 4;
            float4 v = make_float4(0.f, 0.f, 0.f, 0.f);
            if (ok) {
                if (k + 3 < KIN) v = *reinterpret_cast<const float4*>(ar + k);
                else {
                    if (k     < KIN) v.x = ar[k];
                    if (k + 1 < KIN) v.y = ar[k + 1];
                    if (k + 2 < KIN) v.z = ar[k + 2];
                    if (k + 3 < KIN) v.w = ar[k + 3];
                }
            }
            uint32_t h0, l0, h1, l1;
            split2(v.x, v.y, h0, l0);
            split2(v.z, v.w, h1, l1);
            sts32(AHI + a_off(r, k),     h0);
            sts32(AHI + a_off(r, k + 2), h1);
            sts32(ALO + a_off(r, k),     l0);
            sts32(ALO + a_off(r, k + 2), l1);
        }
    }
    // ---- head: stage fc2 fp32 into W2HI region ----
    if (head) {
        float* w2f = (float*)(smem + SM_W2HI);
        for (int i = tid; i < D * NCLS; i += 512) w2f[i] = __ldg(W2f + i);
    }
    // ---- stage params ----
    if (tid < 128) {
        par[tid] = __ldg(b1 + tid);
        if (!head) {
            par[128 + tid] = __ldg(b2 + tid);
            par[256 + tid] = __ldg(gamma + tid) * rsqrtf(__ldg(var + tid) + 1e-5f);
            par[384 + tid] = __ldg(mean + tid);
            par[512 + tid] = __ldg(beta + tid);
        } else if (tid < NCLS) {
            par[128 + tid] = __ldg(b2 + tid);
        }
    }
    CP_WAIT(1);          // W1 tiles resident (this thread); barrier makes global
    __syncthreads();

    const int r0 = wr * 32 + (lane >> 2);
    const int cc = (lane & 3) * 2;
    const int n0 = wc * 32;

    // ---- GEMM1 ----
    float acc[2][4][4];
#pragma unroll
    for (int m = 0; m < 2; m++)
#pragma unroll
        for (int t = 0; t < 4; t++)
#pragma unroll
            for (int j = 0; j < 4; j++) acc[m][t][j] = 0.f;
    gemm_split(AHI, ALO, W1HI, W1LO, r0, cc, n0, lane, acc, KPAD);
    __syncthreads();   // all A/W1 reads done before overwriting A with T

    // ---- epilogue1: T = relu(acc + b1) -> back into A slots ----
    if (!head) {
#pragma unroll
        for (int m = 0; m < 2; m++) {
            int rm = r0 + m * 16;
#pragma unroll
            for (int t = 0; t < 4; t++) {
                int c0 = n0 + t * 8 + cc;
                float x0 = fmaxf(acc[m][t][0] + par[c0], 0.f);
                float x1 = fmaxf(acc[m][t][1] + par[c0 + 1], 0.f);
                float x2 = fmaxf(acc[m][t][2] + par[c0], 0.f);
                float x3 = fmaxf(acc[m][t][3] + par[c0 + 1], 0.f);
                uint32_t h, l;
                split2(x0, x1, h, l);
                sts32(AHI + a_off(rm, c0), h);
                sts32(ALO + a_off(rm, c0), l);
                split2(x2, x3, h, l);
                sts32(AHI + a_off(rm + 8, c0), h);
                sts32(ALO + a_off(rm + 8, c0), l);
            }
        }
    } else {
        float* Tf = (float*)(smem + SM_AHI);   // fp32, stride 132
#pragma unroll
        for (int m = 0; m < 2; m++) {
            int rm = r0 + m * 16;
#pragma unroll
            for (int t = 0; t < 4; t++) {
                int c0 = n0 + t * 8 + cc;
                Tf[rm * 132 + c0]           = fmaxf(acc[m][t][0] + par[c0], 0.f);
                Tf[rm * 132 + c0 + 1]       = fmaxf(acc[m][t][1] + par[c0 + 1], 0.f);
                Tf[(rm + 8) * 132 + c0]     = fmaxf(acc[m][t][2] + par[c0], 0.f);
                Tf[(rm + 8) * 132 + c0 + 1] = fmaxf(acc[m][t][3] + par[c0 + 1], 0.f);
            }
        }
    }
    CP_WAIT(0);          // W2 tiles resident
    __syncthreads();

    if (head) {
        // ---- fc2 SIMT: out[128x6] = T @ W2f + b2 ----
        if (tid < 128) {
            const float* Tf = (const float*)(smem + SM_AHI);
            const float* Wf = (const float*)(smem + SM_W2HI);
            float a6[NCLS];
#pragma unroll
            for (int c = 0; c < NCLS; c++) a6[c] = par[128 + c];
            for (int kk = 0; kk < D; kk++) {
                int k = (kk + lane) & (D - 1);
                float tv = Tf[tid * 132 + k];
#pragma unroll
                for (int c = 0; c < NCLS; c++) a6[c] += tv * Wf[k * NCLS + c];
            }
            if (row0 + tid < NN)
#pragma unroll
                for (int c = 0; c < NCLS; c++) out[(size_t)(row0 + tid) * NCLS + c] = a6[c];
        }
        return;
    }

    // ---- GEMM2 ----
#pragma unroll
    for (int m = 0; m < 2; m++)
#pragma unroll
        for (int t = 0; t < 4; t++)
#pragma unroll
            for (int j = 0; j < 4; j++) acc[m][t][j] = 0.f;
    gemm_split(AHI, ALO, W2HI, W2LO, r0, cc, n0, lane, acc, 128);

    // ---- epilogue2: BN(relu(acc + b2)) -> gmem fp32 + fp16 copy ----
#pragma unroll
    for (int m = 0; m < 2; m++) {
        int g0 = row0 + r0 + m * 16, g1 = g0 + 8;
#pragma unroll
        for (int t = 0; t < 4; t++) {
            int c0 = n0 + t * 8 + cc;
            float b0v = par[128 + c0], b1v = par[128 + c0 + 1];
            float s0 = par[256 + c0],  s1 = par[256 + c0 + 1];
            float m0 = par[384 + c0],  m1 = par[384 + c0 + 1];
            float t0 = par[512 + c0],  t1 = par[512 + c0 + 1];
            if (g0 < NN) {
                float v0 = (fmaxf(acc[m][t][0] + b0v, 0.f) - m0) * s0 + t0;
                float v1 = (fmaxf(acc[m][t][1] + b1v, 0.f) - m1) * s1 + t1;
                *reinterpret_cast<float2*>(out + (size_t)g0 * D + c0) = make_float2(v0, v1);
                *reinterpret_cast<__half2*>(out16 + (size_t)g0 * D + c0) =
                    __floats2half2_rn(v0, v1);
            }
            if (g1 < NN) {
                float v2 = (fmaxf(acc[m][t][2] + b0v, 0.f) - m0) * s0 + t0;
                float v3 = (fmaxf(acc[m][t][3] + b1v, 0.f) - m1) * s1 + t1;
                *reinterpret_cast<float2*>(out + (size_t)g1 * D + c0) = make_float2(v2, v3);
                *reinterpret_cast<__half2*>(out16 + (size_t)g1 * D + c0) =
                    __floats2half2_rn(v2, v3);
            }
        }
    }
}

// ---------------- launch ----------------------------------------------------
extern "C" void kernel_launch(void* const* d_in, const int* in_sizes, int n_in,
                              void* d_out, int out_size) {
    const float* x      = (const float*)d_in[0];
    const void*  ei     = (const void*)d_in[1];
    const float* w1_0   = (const float*)d_in[2];
    const float* b1_0   = (const float*)d_in[3];
    const float* w2_0   = (const float*)d_in[4];
    const float* b2_0   = (const float*)d_in[5];
    const float* ws1    = (const float*)d_in[6];
    const float* bs1    = (const float*)d_in[7];
    const float* ws2    = (const float*)d_in[8];
    const float* bs2    = (const float*)d_in[9];
    const float* gammas = (const float*)d_in[10];
    const float* betas  = (const float*)d_in[11];
    const float* means  = (const float*)d_in[12];
    const float* vars   = (const float*)d_in[13];
    const float* fc1_w  = (const float*)d_in[14];
    const float* fc1_b  = (const float*)d_in[15];
    const float* fc2_w  = (const float*)d_in[16];
    const float* fc2_b  = (const float*)d_in[17];
    float* out = (float*)d_out;

    float *agg12, *hA, *hB, *agg;
    __half *h16A, *h16B;
    uint32_t* wt;
    cudaGetSymbolAddress((void**)&agg12, g_agg12);
    cudaGetSymbolAddress((void**)&hA, g_hA);
    cudaGetSymbolAddress((void**)&hB, g_hB);
    cudaGetSymbolAddress((void**)&h16A, g_h16A);
    cudaGetSymbolAddress((void**)&h16B, g_h16B);
    cudaGetSymbolAddress((void**)&agg, g_agg);
    cudaGetSymbolAddress((void**)&wt, g_wt);
    auto tile = [&](int t, int half) -> const uint32_t* {
        return wt + ((size_t)t * 2 + half) * TILE_WORDS;
    };

    cudaFuncSetAttribute(mlp_mma<12, 16>, cudaFuncAttributeMaxDynamicSharedMemorySize, SM_TOTAL);
    cudaFuncSetAttribute(mlp_mma<128, 128>, cudaFuncAttributeMaxDynamicSharedMemorySize, SM_TOTAL);

    const int TC_GRID = (NN + 127) / 128;             // 391
    const int WARP_GRID = (NN * 32 + 255) / 256;      // one warp per node

    // ---- weight prep + CSR build ----
    prep_weights_kernel<<<(NTILES * 128 * 68 + 255) / 256, 256>>>(w1_0, w2_0, ws1, ws2, fc1_w);
    detect_zero_kernel<<<(NN + 255) / 256, 256>>>(ei);
    hist_kernel<<<(NE + 255) / 256, 256>>>(ei);
    scan_lookback_kernel<<<NBLK, 1024>>>();
    fill_kernel<<<(NE + 255) / 256, 256>>>(ei);

    // ---- layer 1 (nfeat=12): gather + MLP -> hA/h16A ----
    gather12_kernel<<<WARP_GRID, 256>>>(x);
    mlp_mma<12, 16><<<TC_GRID, 512, SM_TOTAL>>>(agg12,
                                                tile(0, 0), tile(0, 1), tile(1, 0), tile(1, 1),
                                                b1_0, nullptr, b2_0,
                                                gammas, betas, means, vars, hA, h16A, 0);

    // ---- layers 2-5: standalone gather (high occupancy), ping-pong h ----
    for (int i = 0; i < 4; i++) {
        const float*  hin   = (i & 1) ? hB   : hA;
        const __half* h16in = (i & 1) ? h16B : h16A;
        float*  hout   = (i & 1) ? hA   : hB;
        __half* h16out = (i & 1) ? h16A : h16B;
        gather128_h16_kernel<<<WARP_GRID, 256>>>(h16in, hin, agg);
        mlp_mma<128, 128><<<TC_GRID, 512, SM_TOTAL>>>(agg,
                                                      tile(2 + 2 * i, 0), tile(2 + 2 * i, 1),
                                                      tile(3 + 2 * i, 0), tile(3 + 2 * i, 1),
                                                      bs1 + i * D, nullptr, bs2 + i * D,
                                                      gammas + (i + 1) * D, betas + (i + 1) * D,
                                                      means + (i + 1) * D, vars + (i + 1) * D,
                                                      hout, h16out, 0);
    }

    // ---- head: fc1 (mma, pre-split tile) + fc2 (SIMT fp32) ----
    mlp_mma<128, 128><<<TC_GRID, 512, SM_TOTAL>>>(hA,
                                                  tile(10, 0), tile(10, 1),
                                                  tile(10, 0), tile(10, 1),   // unused (head)
                                                  fc1_b, fc2_w, fc2_b,
                                                  nullptr, nullptr, nullptr, nullptr,
                                                  out, nullptr, 1);
}

// round 16
// speedup vs baseline: 1.3332x; 1.0399x over previous
#include <cuda_runtime.h>
#include <cuda_bf16.h>
#include <cuda_fp16.h>
#include <cstdint>

#define NN   50000
#define NE   1600000
#define D    128
#define NCLS 6
#define NBLK 49          // ceil(NN / 1024) scan blocks
#define NTILES 11        // pre-split weight tiles
#define TILE_WORDS 8704  // 34816 B / 4
#define NROWTILE 391     // ceil(NN/128)
#define PGRID 148        // persistent grid (SM count)

// ---------------- scratch (static device globals; no runtime allocation) ----
__device__ float  g_agg12[NN * 12];
__device__ float  g_hA[(size_t)NN * D];
__device__ float  g_hB[(size_t)NN * D];
__device__ __half g_h16A[(size_t)NN * D];
__device__ __half g_h16B[(size_t)NN * D];
__device__ float  g_agg[(size_t)NN * D];
__device__ int    g_counts[NN];
__device__ int    g_rowptr[NN + 1];
__device__ int    g_cursor[NN];
__device__ int    g_col[NE];
__device__ volatile int g_scan_val[64];
__device__ volatile int g_scan_flag[64];
__device__ int    g_is64;
// pre-split weight tile images: [tile][hi/lo][words]
__device__ uint32_t g_wt[NTILES][2][TILE_WORDS];

// ---------------- small helpers ---------------------------------------------
__device__ __forceinline__ uint32_t smem_to_u32(const void* p) {
    uint32_t a;
    asm("{ .reg .u64 t; cvta.to.shared.u64 t, %1; cvt.u32.u64 %0, t; }"
        : "=r"(a) : "l"(p));
    return a;
}
__device__ __forceinline__ uint32_t lds32(uint32_t addr) {
    uint32_t v;
    asm volatile("ld.shared.b32 %0, [%1];" : "=r"(v) : "r"(addr));
    return v;
}
__device__ __forceinline__ void sts32(uint32_t addr, uint32_t v) {
    asm volatile("st.shared.b32 [%0], %1;" :: "r"(addr), "r"(v) : "memory");
}
#define CP_ASYNC16(smem, gptr) \
    asm volatile("cp.async.cg.shared.global [%0], [%1], 16;" \
                 :: "r"(smem), "l"(gptr) : "memory")
#define CP_COMMIT() asm volatile("cp.async.commit_group;" ::: "memory")
#define CP_WAIT(n)  asm volatile("cp.async.wait_group %0;" :: "n"(n) : "memory")

// split two fp32 into bf16 hi/lo packed pairs
__device__ __forceinline__ void split2(float x, float y, uint32_t& hi, uint32_t& lo) {
    __nv_bfloat16 xh = __float2bfloat16(x), yh = __float2bfloat16(y);
    float xr = x - __bfloat162float(xh);
    float yr = y - __bfloat162float(yh);
    __nv_bfloat16 xl = __float2bfloat16(xr), yl = __float2bfloat16(yr);
    hi = ((uint32_t)__bfloat16_as_ushort(yh) << 16) | __bfloat16_as_ushort(xh);
    lo = ((uint32_t)__bfloat16_as_ushort(yl) << 16) | __bfloat16_as_ushort(xl);
}
__device__ __forceinline__ void mma16816(float* c, const uint32_t* a, const uint32_t* b) {
    asm volatile(
        "mma.sync.aligned.m16n8k16.row.col.f32.bf16.bf16.f32 "
        "{%0,%1,%2,%3},{%4,%5,%6,%7},{%8,%9},{%0,%1,%2,%3};"
        : "+f"(c[0]), "+f"(c[1]), "+f"(c[2]), "+f"(c[3])
        : "r"(a[0]), "r"(a[1]), "r"(a[2]), "r"(a[3]), "r"(b[0]), "r"(b[1]));
}
__device__ __forceinline__ void acc_h2(float4& a, uint2 p) {
    __half2 h0 = *reinterpret_cast<__half2*>(&p.x);
    __half2 h1 = *reinterpret_cast<__half2*>(&p.y);
    float2 f0 = __half22float2(h0);
    float2 f1 = __half22float2(h1);
    a.x += f0.x; a.y += f0.y; a.z += f1.x; a.w += f1.y;
}

// ---------------- smem tile layouts ------------------------------------------
#define KS 136                       // bf16 elems per row (padded)
__device__ __forceinline__ uint32_t a_off(int r, int k) {
    return (uint32_t)(r * KS + k) * 2;
}
// W tile: [n][k] with XOR swizzle on k bits 1..2 keyed by (n>>3)&3.
__device__ __forceinline__ uint32_t wt_off(int n, int k) {
    return (uint32_t)(n * KS + (k ^ ((((unsigned)n >> 3) & 3) << 1))) * 2;
}

#define SM_AHI   0
#define SM_ALO   34816
#define SM_W1HI  69632
#define SM_W1LO  104448
#define SM_W2HI  139264
#define SM_W2LO  174080
#define SM_PAR   208896              // 640 floats: b1|b2|sc|mn|bt
#define SM_TOTAL 211456

// ---------------- prep: pre-split weights into swizzled tile images ---------
// tiles: 0=lay1 W1(kin12), 1=lay1 W2, 2+2i=ws1[i], 3+2i=ws2[i], 10=fc1
__global__ void prep_weights_kernel(const float* __restrict__ w1_0,
                                    const float* __restrict__ w2_0,
                                    const float* __restrict__ ws1,
                                    const float* __restrict__ ws2,
                                    const float* __restrict__ fc1_w) {
    int idx = blockIdx.x * blockDim.x + threadIdx.x;
    if (idx >= NTILES * 128 * 68) return;
    int t = idx / (128 * 68);
    int rem = idx - t * (128 * 68);
    int n = rem / 68;
    int kp = rem - n * 68;
    int k = kp * 2;
    const float* W;
    int kin;
    if (t == 0)       { W = w1_0;  kin = 12; }
    else if (t == 1)  { W = w2_0;  kin = 128; }
    else if (t == 10) { W = fc1_w; kin = 128; }
    else {
        int i = (t - 2) >> 1;
        W = (((t - 2) & 1) == 0 ? ws1 : ws2) + (size_t)i * D * D;
        kin = 128;
    }
    float v0 = (k < kin)     ? __ldg(W + (size_t)k * D + n)       : 0.f;
    float v1 = (k + 1 < kin) ? __ldg(W + (size_t)(k + 1) * D + n) : 0.f;
    uint32_t hi, lo;
    split2(v0, v1, hi, lo);
    uint32_t off = wt_off(n, k) >> 2;
    g_wt[t][0][off] = hi;
    g_wt[t][1][off] = lo;
}

// ---------------- edge dtype detect + zero counts + reset scan flags --------
__global__ void detect_zero_kernel(const void* ei) {
    int i = blockIdx.x * blockDim.x + threadIdx.x;
    if (i < NN) g_counts[i] = 0;
    if (i < 64) { g_scan_flag[i] = 0; g_scan_val[i] = 0; }
    if (i == 0) {
        const long long* p = (const long long*)ei;
        int ok = 1;
        for (int j = 0; j < 64; j++) {
            long long v = p[j];
            if (v < 0 || v >= NN) { ok = 0; break; }
        }
        g_is64 = ok;
    }
}
__device__ __forceinline__ int edge_idx(const void* ei, long long pos, int is64) {
    if (is64) return (int)((const long long*)ei)[pos];
    return ((const int*)ei)[pos];
}

// ---------------- CSR build --------------------------------------------------
__global__ void hist_kernel(const void* __restrict__ ei) {
    int e = blockIdx.x * blockDim.x + threadIdx.x;
    if (e >= NE) return;
    const int is64 = g_is64;
    int dst = edge_idx(ei, (long long)NE + e, is64);
    if ((unsigned)dst < NN) atomicAdd(&g_counts[dst], 1);
}
// exclusive scan with warp-parallel decoupled lookback (49 blocks co-resident)
__global__ void scan_lookback_kernel() {
    __shared__ int sh[1024];
    __shared__ int prefix_s;
    int b = blockIdx.x;
    int i = b * 1024 + threadIdx.x;
    int v = (i < NN) ? g_counts[i] : 0;
    sh[threadIdx.x] = v;
    __syncthreads();
#pragma unroll
    for (int off = 1; off < 1024; off <<= 1) {
        int t = (threadIdx.x >= off) ? sh[threadIdx.x - off] : 0;
        __syncthreads();
        sh[threadIdx.x] += t;
        __syncthreads();
    }
    int total = sh[1023];
    if (threadIdx.x == 0) {
        g_scan_val[b] = total;
        __threadfence();
        g_scan_flag[b] = 1;
    }
    if (threadIdx.x < 32) {
        int pre = 0;
        for (int p = b - 1 - (int)threadIdx.x; p >= 0; p -= 32) {
            while (g_scan_flag[p] == 0) {}
            pre += g_scan_val[p];
        }
#pragma unroll
        for (int off = 16; off > 0; off >>= 1)
            pre += __shfl_down_sync(0xffffffffu, pre, off);
        if (threadIdx.x == 0) {
            prefix_s = pre;
            if (b == NBLK - 1) g_rowptr[NN] = pre + total;
        }
    }
    __syncthreads();
    if (i < NN) {
        int excl = prefix_s + sh[threadIdx.x] - v;
        g_rowptr[i] = excl;
        g_cursor[i] = excl;
    }
}
__global__ void fill_kernel(const void* __restrict__ ei) {
    int e = blockIdx.x * blockDim.x + threadIdx.x;
    if (e >= NE) return;
    const int is64 = g_is64;
    int src = edge_idx(ei, e, is64);
    int dst = edge_idx(ei, (long long)NE + e, is64);
    if ((unsigned)src >= NN || (unsigned)dst >= NN) return;
    int pos = atomicAdd(&g_cursor[dst], 1);
    g_col[pos] = src;
}

// ---------------- CSR gathers ------------------------------------------------
__global__ void gather12_kernel(const float* __restrict__ x) {
    int n = (blockIdx.x * blockDim.x + threadIdx.x) >> 5;
    if (n >= NN) return;
    int lane = threadIdx.x & 31;
    int beg = g_rowptr[n], end = g_rowptr[n + 1];
    float acc = (lane < 12) ? x[(size_t)n * 12 + lane] : 0.f;
    for (int e = beg; e < end; e++) {
        int s = g_col[e];
        if (lane < 12) acc += x[(size_t)s * 12 + lane];
    }
    if (lane < 12) g_agg12[(size_t)n * 12 + lane] = acc;
}
__global__ void gather128_h16_kernel(const __half* __restrict__ h16,
                                     const float* __restrict__ h,
                                     float* __restrict__ agg) {
    int n = (blockIdx.x * blockDim.x + threadIdx.x) >> 5;
    if (n >= NN) return;
    int lane = threadIdx.x & 31;
    int beg = g_rowptr[n], end = g_rowptr[n + 1];
    const int fo = lane * 4;
    float4 acc = *reinterpret_cast<const float4*>(h + (size_t)n * D + fo);
    float4 acc2 = make_float4(0.f, 0.f, 0.f, 0.f);
    int e = beg;
    for (; e + 3 < end; e += 4) {
        int s0 = g_col[e], s1 = g_col[e + 1], s2 = g_col[e + 2], s3 = g_col[e + 3];
        uint2 p0 = *reinterpret_cast<const uint2*>(h16 + (size_t)s0 * D + fo);
        uint2 p1 = *reinterpret_cast<const uint2*>(h16 + (size_t)s1 * D + fo);
        uint2 p2 = *reinterpret_cast<const uint2*>(h16 + (size_t)s2 * D + fo);
        uint2 p3 = *reinterpret_cast<const uint2*>(h16 + (size_t)s3 * D + fo);
        acc_h2(acc, p0);  acc_h2(acc2, p1);
        acc_h2(acc, p2);  acc_h2(acc2, p3);
    }
    for (; e < end; e++) {
        uint2 p = *reinterpret_cast<const uint2*>(h16 + (size_t)g_col[e] * D + fo);
        acc_h2(acc, p);
    }
    acc.x += acc2.x; acc.y += acc2.y; acc.z += acc2.z; acc.w += acc2.w;
    *reinterpret_cast<float4*>(agg + (size_t)n * D + fo) = acc;
}

// ============================================================================
// PERSISTENT mma.sync fused MLP: PGRID CTAs loop over 128-row tiles.
// W tiles cp.async'd ONCE per CTA from pre-split gmem images; params once.
// 512 threads (16 warps, 4x4). bf16 hi/lo split, 3 passes, fp32 accum.
// head==0: out = BN(relu(relu(A@W1+b1)@W2+b2)), + fp16 copy to out16.
// head==1: fc1 (mma) + fc2 (SIMT, fp32 W2f).
// ============================================================================
__device__ __forceinline__ void gemm_split(
    uint32_t aHi, uint32_t aLo, uint32_t wHi, uint32_t wLo,
    int r0, int cc, int n0, int lane, float acc[2][4][4], int kpad) {
#pragma unroll 2
    for (int kb = 0; kb < kpad; kb += 16) {
        uint32_t ah[2][4], al[2][4];
#pragma unroll
        for (int m = 0; m < 2; m++) {
            int rm = r0 + m * 16;
            ah[m][0] = lds32(aHi + a_off(rm,     kb + cc));
            ah[m][1] = lds32(aHi + a_off(rm + 8, kb + cc));
            ah[m][2] = lds32(aHi + a_off(rm,     kb + cc + 8));
            ah[m][3] = lds32(aHi + a_off(rm + 8, kb + cc + 8));
            al[m][0] = lds32(aLo + a_off(rm,     kb + cc));
            al[m][1] = lds32(aLo + a_off(rm + 8, kb + cc));
            al[m][2] = lds32(aLo + a_off(rm,     kb + cc + 8));
            al[m][3] = lds32(aLo + a_off(rm + 8, kb + cc + 8));
        }
#pragma unroll
        for (int t = 0; t < 4; t++) {
            int nl = n0 + t * 8 + (lane >> 2);
            uint32_t bh[2], bl[2];
            bh[0] = lds32(wHi + wt_off(nl, kb + cc));
            bh[1] = lds32(wHi + wt_off(nl, kb + cc + 8));
            bl[0] = lds32(wLo + wt_off(nl, kb + cc));
            bl[1] = lds32(wLo + wt_off(nl, kb + cc + 8));
            mma16816(acc[0][t], ah[0], bh);
            mma16816(acc[1][t], ah[1], bh);
            mma16816(acc[0][t], al[0], bh);
            mma16816(acc[1][t], al[1], bh);
            mma16816(acc[0][t], ah[0], bl);
            mma16816(acc[1][t], ah[1], bl);
        }
    }
}

template <int KIN, int KPAD>
__global__ __launch_bounds__(512, 1) void mlp_mma(
    const float* __restrict__ A,
    const uint32_t* __restrict__ w1hi, const uint32_t* __restrict__ w1lo,
    const uint32_t* __restrict__ w2hi, const uint32_t* __restrict__ w2lo,
    const float* __restrict__ b1,
    const float* __restrict__ W2f, const float* __restrict__ b2,
    const float* __restrict__ gamma, const float* __restrict__ beta,
    const float* __restrict__ mean, const float* __restrict__ var,
    float* __restrict__ out, __half* __restrict__ out16, int head) {
    extern __shared__ char smem[];
    const uint32_t sb = smem_to_u32(smem);
    const int tid = threadIdx.x;
    const int lane = tid & 31;
    const int wid = tid >> 5;
    const int wr = wid >> 2, wc = wid & 3;    // 4 x 4 warps

    const uint32_t AHI = sb + SM_AHI, ALO = sb + SM_ALO;
    const uint32_t W1HI = sb + SM_W1HI, W1LO = sb + SM_W1LO;
    const uint32_t W2HI = sb + SM_W2HI, W2LO = sb + SM_W2LO;
    float* par = (float*)(smem + SM_PAR);   // b1[128] b2[128] sc[128] mn[128] bt[128]

    // ---- ONCE: async W tile copies ----
    for (int i = tid; i < 2176; i += 512) {
        CP_ASYNC16(W1HI + i * 16, (const char*)w1hi + i * 16);
        CP_ASYNC16(W1LO + i * 16, (const char*)w1lo + i * 16);
    }
    if (!head) {
        for (int i = tid; i < 2176; i += 512) {
            CP_ASYNC16(W2HI + i * 16, (const char*)w2hi + i * 16);
            CP_ASYNC16(W2LO + i * 16, (const char*)w2lo + i * 16);
        }
    }
    CP_COMMIT();
    // ---- ONCE: head fc2 fp32, params ----
    if (head) {
        float* w2f = (float*)(smem + SM_W2HI);
        for (int i = tid; i < D * NCLS; i += 512) w2f[i] = __ldg(W2f + i);
    }
    if (tid < 128) {
        par[tid] = __ldg(b1 + tid);
        if (!head) {
            par[128 + tid] = __ldg(b2 + tid);
            par[256 + tid] = __ldg(gamma + tid) * rsqrtf(__ldg(var + tid) + 1e-5f);
            par[384 + tid] = __ldg(mean + tid);
            par[512 + tid] = __ldg(beta + tid);
        } else if (tid < NCLS) {
            par[128 + tid] = __ldg(b2 + tid);
        }
    }

    const int r0 = wr * 32 + (lane >> 2);
    const int cc = (lane & 3) * 2;
    const int n0 = wc * 32;
    bool wfirst = true;

    for (int tile = blockIdx.x; tile < NROWTILE; tile += gridDim.x) {
        const int row0 = tile * 128;

        // ---- stage A [row][k] hi/lo ----
        {
            int r = tid >> 2, q = tid & 3;
            int gr = row0 + r;
            const float* ar = A + (size_t)gr * KIN;
            bool ok = gr < NN;
#pragma unroll
            for (int j = 0; j < KPAD / 16; j++) {
                int k = q * (KPAD / 4) + j * 4;
                float4 v = make_float4(0.f, 0.f, 0.f, 0.f);
                if (ok) {
                    if (k + 3 < KIN) v = *reinterpret_cast<const float4*>(ar + k);
                    else {
                        if (k     < KIN) v.x = ar[k];
                        if (k + 1 < KIN) v.y = ar[k + 1];
                        if (k + 2 < KIN) v.z = ar[k + 2];
                        if (k + 3 < KIN) v.w = ar[k + 3];
                    }
                }
                uint32_t h0, l0, h1, l1;
                split2(v.x, v.y, h0, l0);
                split2(v.z, v.w, h1, l1);
                sts32(AHI + a_off(r, k),     h0);
                sts32(AHI + a_off(r, k + 2), h1);
                sts32(ALO + a_off(r, k),     l0);
                sts32(ALO + a_off(r, k + 2), l1);
            }
        }
        if (wfirst) { CP_WAIT(0); wfirst = false; }
        __syncthreads();

        // ---- GEMM1 ----
        float acc[2][4][4];
#pragma unroll
        for (int m = 0; m < 2; m++)
#pragma unroll
            for (int t = 0; t < 4; t++)
#pragma unroll
                for (int j = 0; j < 4; j++) acc[m][t][j] = 0.f;
        gemm_split(AHI, ALO, W1HI, W1LO, r0, cc, n0, lane, acc, KPAD);
        __syncthreads();

        // ---- epilogue1: T = relu(acc + b1) -> back into A slots ----
        if (!head) {
#pragma unroll
            for (int m = 0; m < 2; m++) {
                int rm = r0 + m * 16;
#pragma unroll
                for (int t = 0; t < 4; t++) {
                    int c0 = n0 + t * 8 + cc;
                    float x0 = fmaxf(acc[m][t][0] + par[c0], 0.f);
                    float x1 = fmaxf(acc[m][t][1] + par[c0 + 1], 0.f);
                    float x2 = fmaxf(acc[m][t][2] + par[c0], 0.f);
                    float x3 = fmaxf(acc[m][t][3] + par[c0 + 1], 0.f);
                    uint32_t h, l;
                    split2(x0, x1, h, l);
                    sts32(AHI + a_off(rm, c0), h);
                    sts32(ALO + a_off(rm, c0), l);
                    split2(x2, x3, h, l);
                    sts32(AHI + a_off(rm + 8, c0), h);
                    sts32(ALO + a_off(rm + 8, c0), l);
                }
            }
        } else {
            float* Tf = (float*)(smem + SM_AHI);   // fp32, stride 132
#pragma unroll
            for (int m = 0; m < 2; m++) {
                int rm = r0 + m * 16;
#pragma unroll
                for (int t = 0; t < 4; t++) {
                    int c0 = n0 + t * 8 + cc;
                    Tf[rm * 132 + c0]           = fmaxf(acc[m][t][0] + par[c0], 0.f);
                    Tf[rm * 132 + c0 + 1]       = fmaxf(acc[m][t][1] + par[c0 + 1], 0.f);
                    Tf[(rm + 8) * 132 + c0]     = fmaxf(acc[m][t][2] + par[c0], 0.f);
                    Tf[(rm + 8) * 132 + c0 + 1] = fmaxf(acc[m][t][3] + par[c0 + 1], 0.f);
                }
            }
        }
        __syncthreads();

        if (head) {
            // ---- fc2 SIMT: out[128x6] = T @ W2f + b2 ----
            if (tid < 128) {
                const float* Tf = (const float*)(smem + SM_AHI);
                const float* Wf = (const float*)(smem + SM_W2HI);
                float a6[NCLS];
#pragma unroll
                for (int c = 0; c < NCLS; c++) a6[c] = par[128 + c];
                for (int kk = 0; kk < D; kk++) {
                    int k = (kk + lane) & (D - 1);
                    float tv = Tf[tid * 132 + k];
#pragma unroll
                    for (int c = 0; c < NCLS; c++) a6[c] += tv * Wf[k * NCLS + c];
                }
                if (row0 + tid < NN)
#pragma unroll
                    for (int c = 0; c < NCLS; c++)
                        out[(size_t)(row0 + tid) * NCLS + c] = a6[c];
            }
            __syncthreads();   // Tf reads done before next tile's A staging
            continue;
        }

        // ---- GEMM2 ----
#pragma unroll
        for (int m = 0; m < 2; m++)
#pragma unroll
            for (int t = 0; t < 4; t++)
#pragma unroll
                for (int j = 0; j < 4; j++) acc[m][t][j] = 0.f;
        gemm_split(AHI, ALO, W2HI, W2LO, r0, cc, n0, lane, acc, 128);

        // ---- epilogue2: BN(relu(acc + b2)) -> gmem fp32 + fp16 copy ----
#pragma unroll
        for (int m = 0; m < 2; m++) {
            int g0 = row0 + r0 + m * 16, g1 = g0 + 8;
#pragma unroll
            for (int t = 0; t < 4; t++) {
                int c0 = n0 + t * 8 + cc;
                float b0v = par[128 + c0], b1v = par[128 + c0 + 1];
                float s0 = par[256 + c0],  s1 = par[256 + c0 + 1];
                float m0 = par[384 + c0],  m1 = par[384 + c0 + 1];
                float t0 = par[512 + c0],  t1 = par[512 + c0 + 1];
                if (g0 < NN) {
                    float v0 = (fmaxf(acc[m][t][0] + b0v, 0.f) - m0) * s0 + t0;
                    float v1 = (fmaxf(acc[m][t][1] + b1v, 0.f) - m1) * s1 + t1;
                    *reinterpret_cast<float2*>(out + (size_t)g0 * D + c0) = make_float2(v0, v1);
                    *reinterpret_cast<__half2*>(out16 + (size_t)g0 * D + c0) =
                        __floats2half2_rn(v0, v1);
                }
                if (g1 < NN) {
                    float v2 = (fmaxf(acc[m][t][2] + b0v, 0.f) - m0) * s0 + t0;
                    float v3 = (fmaxf(acc[m][t][3] + b1v, 0.f) - m1) * s1 + t1;
                    *reinterpret_cast<float2*>(out + (size_t)g1 * D + c0) = make_float2(v2, v3);
                    *reinterpret_cast<__half2*>(out16 + (size_t)g1 * D + c0) =
                        __floats2half2_rn(v2, v3);
                }
            }
        }
        __syncthreads();   // GEMM2 smem reads done before next tile's A staging
    }
}

// ---------------- launch ----------------------------------------------------
extern "C" void kernel_launch(void* const* d_in, const int* in_sizes, int n_in,
                              void* d_out, int out_size) {
    const float* x      = (const float*)d_in[0];
    const void*  ei     = (const void*)d_in[1];
    const float* w1_0   = (const float*)d_in[2];
    const float* b1_0   = (const float*)d_in[3];
    const float* w2_0   = (const float*)d_in[4];
    const float* b2_0   = (const float*)d_in[5];
    const float* ws1    = (const float*)d_in[6];
    const float* bs1    = (const float*)d_in[7];
    const float* ws2    = (const float*)d_in[8];
    const float* bs2    = (const float*)d_in[9];
    const float* gammas = (const float*)d_in[10];
    const float* betas  = (const float*)d_in[11];
    const float* means  = (const float*)d_in[12];
    const float* vars   = (const float*)d_in[13];
    const float* fc1_w  = (const float*)d_in[14];
    const float* fc1_b  = (const float*)d_in[15];
    const float* fc2_w  = (const float*)d_in[16];
    const float* fc2_b  = (const float*)d_in[17];
    float* out = (float*)d_out;

    float *agg12, *hA, *hB, *agg;
    __half *h16A, *h16B;
    uint32_t* wt;
    cudaGetSymbolAddress((void**)&agg12, g_agg12);
    cudaGetSymbolAddress((void**)&hA, g_hA);
    cudaGetSymbolAddress((void**)&hB, g_hB);
    cudaGetSymbolAddress((void**)&h16A, g_h16A);
    cudaGetSymbolAddress((void**)&h16B, g_h16B);
    cudaGetSymbolAddress((void**)&agg, g_agg);
    cudaGetSymbolAddress((void**)&wt, g_wt);
    auto tile = [&](int t, int half) -> const uint32_t* {
        return wt + ((size_t)t * 2 + half) * TILE_WORDS;
    };

    cudaFuncSetAttribute(mlp_mma<12, 16>, cudaFuncAttributeMaxDynamicSharedMemorySize, SM_TOTAL);
    cudaFuncSetAttribute(mlp_mma<128, 128>, cudaFuncAttributeMaxDynamicSharedMemorySize, SM_TOTAL);

    const int WARP_GRID = (NN * 32 + 255) / 256;      // one warp per node

    // ---- weight prep + CSR build ----
    prep_weights_kernel<<<(NTILES * 128 * 68 + 255) / 256, 256>>>(w1_0, w2_0, ws1, ws2, fc1_w);
    detect_zero_kernel<<<(NN + 255) / 256, 256>>>(ei);
    hist_kernel<<<(NE + 255) / 256, 256>>>(ei);
    scan_lookback_kernel<<<NBLK, 1024>>>();
    fill_kernel<<<(NE + 255) / 256, 256>>>(ei);

    // ---- layer 1 (nfeat=12): gather + MLP -> hA/h16A ----
    gather12_kernel<<<WARP_GRID, 256>>>(x);
    mlp_mma<12, 16><<<PGRID, 512, SM_TOTAL>>>(agg12,
                                              tile(0, 0), tile(0, 1), tile(1, 0), tile(1, 1),
                                              b1_0, nullptr, b2_0,
                                              gammas, betas, means, vars, hA, h16A, 0);

    // ---- layers 2-5: standalone gather (high occupancy), ping-pong h ----
    for (int i = 0; i < 4; i++) {
        const float*  hin   = (i & 1) ? hB   : hA;
        const __half* h16in = (i & 1) ? h16B : h16A;
        float*  hout   = (i & 1) ? hA   : hB;
        __half* h16out = (i & 1) ? h16A : h16B;
        gather128_h16_kernel<<<WARP_GRID, 256>>>(h16in, hin, agg);
        mlp_mma<128, 128><<<PGRID, 512, SM_TOTAL>>>(agg,
                                                    tile(2 + 2 * i, 0), tile(2 + 2 * i, 1),
                                                    tile(3 + 2 * i, 0), tile(3 + 2 * i, 1),
                                                    bs1 + i * D, nullptr, bs2 + i * D,
                                                    gammas + (i + 1) * D, betas + (i + 1) * D,
                                                    means + (i + 1) * D, vars + (i + 1) * D,
                                                    hout, h16out, 0);
    }

    // ---- head: fc1 (mma, pre-split tile) + fc2 (SIMT fp32) ----
    mlp_mma<128, 128><<<PGRID, 512, SM_TOTAL>>>(hA,
                                                tile(10, 0), tile(10, 1),
                                                tile(10, 0), tile(10, 1),   // unused (head)
                                                fc1_b, fc2_w, fc2_b,
                                                nullptr, nullptr, nullptr, nullptr,
                                                out, nullptr, 1);
}

// round 17
// speedup vs baseline: 1.3842x; 1.0382x over previous
#include <cuda_runtime.h>
#include <cuda_bf16.h>
#include <cuda_fp16.h>
#include <cstdint>

#define NN   50000
#define NE   1600000
#define D    128
#define NCLS 6
#define NBLK 49          // ceil(NN / 1024) scan blocks
#define NTILES 11        // pre-split weight tiles
#define TILE_WORDS 8704  // 34816 B / 4 (A and W tiles share geometry)
#define NROWTILE 391     // ceil(NN/128)
#define PGRID 148        // persistent grid (SM count)

// ---------------- scratch (static device globals; no runtime allocation) ----
__device__ float  g_agg12[NN * 12];
__device__ float  g_hA[(size_t)NN * D];
__device__ float  g_hB[(size_t)NN * D];
__device__ __half g_h16A[(size_t)NN * D];
__device__ __half g_h16B[(size_t)NN * D];
__device__ int    g_counts[NN];
__device__ int    g_rowptr[NN + 1];
__device__ int    g_cursor[NN];
__device__ int    g_col[NE];
__device__ volatile int g_scan_val[64];
__device__ volatile int g_scan_flag[64];
__device__ int    g_is64;
// pre-split weight tile images: [tile][hi/lo][words]
__device__ uint32_t g_wt[NTILES][2][TILE_WORDS];
// pre-split aggregated-A tile images (written by gather, cp.async'd by MLP)
__device__ uint32_t g_aggHI[(size_t)NROWTILE * TILE_WORDS];
__device__ uint32_t g_aggLO[(size_t)NROWTILE * TILE_WORDS];

// ---------------- small helpers ---------------------------------------------
__device__ __forceinline__ uint32_t smem_to_u32(const void* p) {
    uint32_t a;
    asm("{ .reg .u64 t; cvta.to.shared.u64 t, %1; cvt.u32.u64 %0, t; }"
        : "=r"(a) : "l"(p));
    return a;
}
__device__ __forceinline__ uint32_t lds32(uint32_t addr) {
    uint32_t v;
    asm volatile("ld.shared.b32 %0, [%1];" : "=r"(v) : "r"(addr));
    return v;
}
__device__ __forceinline__ void sts32(uint32_t addr, uint32_t v) {
    asm volatile("st.shared.b32 [%0], %1;" :: "r"(addr), "r"(v) : "memory");
}
#define CP_ASYNC16(smem, gptr) \
    asm volatile("cp.async.cg.shared.global [%0], [%1], 16;" \
                 :: "r"(smem), "l"(gptr) : "memory")
#define CP_COMMIT() asm volatile("cp.async.commit_group;" ::: "memory")
#define CP_WAIT(n)  asm volatile("cp.async.wait_group %0;" :: "n"(n) : "memory")

// split two fp32 into bf16 hi/lo packed pairs
__device__ __forceinline__ void split2(float x, float y, uint32_t& hi, uint32_t& lo) {
    __nv_bfloat16 xh = __float2bfloat16(x), yh = __float2bfloat16(y);
    float xr = x - __bfloat162float(xh);
    float yr = y - __bfloat162float(yh);
    __nv_bfloat16 xl = __float2bfloat16(xr), yl = __float2bfloat16(yr);
    hi = ((uint32_t)__bfloat16_as_ushort(yh) << 16) | __bfloat16_as_ushort(xh);
    lo = ((uint32_t)__bfloat16_as_ushort(yl) << 16) | __bfloat16_as_ushort(xl);
}
__device__ __forceinline__ void mma16816(float* c, const uint32_t* a, const uint32_t* b) {
    asm volatile(
        "mma.sync.aligned.m16n8k16.row.col.f32.bf16.bf16.f32 "
        "{%0,%1,%2,%3},{%4,%5,%6,%7},{%8,%9},{%0,%1,%2,%3};"
        : "+f"(c[0]), "+f"(c[1]), "+f"(c[2]), "+f"(c[3])
        : "r"(a[0]), "r"(a[1]), "r"(a[2]), "r"(a[3]), "r"(b[0]), "r"(b[1]));
}
__device__ __forceinline__ void acc_h2(float4& a, uint2 p) {
    __half2 h0 = *reinterpret_cast<__half2*>(&p.x);
    __half2 h1 = *reinterpret_cast<__half2*>(&p.y);
    float2 f0 = __half22float2(h0);
    float2 f1 = __half22float2(h1);
    a.x += f0.x; a.y += f0.y; a.z += f1.x; a.w += f1.y;
}

// ---------------- smem tile layouts ------------------------------------------
#define KS 136                       // bf16 elems per row (padded)
__device__ __forceinline__ uint32_t a_off(int r, int k) {
    return (uint32_t)(r * KS + k) * 2;
}
// W tile: [n][k] with XOR swizzle on k bits 1..2 keyed by (n>>3)&3.
__device__ __forceinline__ uint32_t wt_off(int n, int k) {
    return (uint32_t)(n * KS + (k ^ ((((unsigned)n >> 3) & 3) << 1))) * 2;
}

#define SM_AHI   0
#define SM_ALO   34816
#define SM_W1HI  69632
#define SM_W1LO  104448
#define SM_W2HI  139264
#define SM_W2LO  174080
#define SM_PAR   208896              // 640 floats: b1|b2|sc|mn|bt
#define SM_TOTAL 211456

// ---------------- prep: pre-split weights into swizzled tile images ---------
// tiles: 0=lay1 W1(kin12), 1=lay1 W2, 2+2i=ws1[i], 3+2i=ws2[i], 10=fc1
__global__ void prep_weights_kernel(const float* __restrict__ w1_0,
                                    const float* __restrict__ w2_0,
                                    const float* __restrict__ ws1,
                                    const float* __restrict__ ws2,
                                    const float* __restrict__ fc1_w) {
    int idx = blockIdx.x * blockDim.x + threadIdx.x;
    if (idx >= NTILES * 128 * 68) return;
    int t = idx / (128 * 68);
    int rem = idx - t * (128 * 68);
    int n = rem / 68;
    int kp = rem - n * 68;
    int k = kp * 2;
    const float* W;
    int kin;
    if (t == 0)       { W = w1_0;  kin = 12; }
    else if (t == 1)  { W = w2_0;  kin = 128; }
    else if (t == 10) { W = fc1_w; kin = 128; }
    else {
        int i = (t - 2) >> 1;
        W = (((t - 2) & 1) == 0 ? ws1 : ws2) + (size_t)i * D * D;
        kin = 128;
    }
    float v0 = (k < kin)     ? __ldg(W + (size_t)k * D + n)       : 0.f;
    float v1 = (k + 1 < kin) ? __ldg(W + (size_t)(k + 1) * D + n) : 0.f;
    uint32_t hi, lo;
    split2(v0, v1, hi, lo);
    uint32_t off = wt_off(n, k) >> 2;
    g_wt[t][0][off] = hi;
    g_wt[t][1][off] = lo;
}

// ---------------- edge dtype detect + zero counts + reset scan flags --------
__global__ void detect_zero_kernel(const void* ei) {
    int i = blockIdx.x * blockDim.x + threadIdx.x;
    if (i < NN) g_counts[i] = 0;
    if (i < 64) { g_scan_flag[i] = 0; g_scan_val[i] = 0; }
    if (i == 0) {
        const long long* p = (const long long*)ei;
        int ok = 1;
        for (int j = 0; j < 64; j++) {
            long long v = p[j];
            if (v < 0 || v >= NN) { ok = 0; break; }
        }
        g_is64 = ok;
    }
}
__device__ __forceinline__ int edge_idx(const void* ei, long long pos, int is64) {
    if (is64) return (int)((const long long*)ei)[pos];
    return ((const int*)ei)[pos];
}

// ---------------- CSR build --------------------------------------------------
__global__ void hist_kernel(const void* __restrict__ ei) {
    int e = blockIdx.x * blockDim.x + threadIdx.x;
    if (e >= NE) return;
    const int is64 = g_is64;
    int dst = edge_idx(ei, (long long)NE + e, is64);
    if ((unsigned)dst < NN) atomicAdd(&g_counts[dst], 1);
}
// exclusive scan with warp-parallel decoupled lookback (49 blocks co-resident)
__global__ void scan_lookback_kernel() {
    __shared__ int sh[1024];
    __shared__ int prefix_s;
    int b = blockIdx.x;
    int i = b * 1024 + threadIdx.x;
    int v = (i < NN) ? g_counts[i] : 0;
    sh[threadIdx.x] = v;
    __syncthreads();
#pragma unroll
    for (int off = 1; off < 1024; off <<= 1) {
        int t = (threadIdx.x >= off) ? sh[threadIdx.x - off] : 0;
        __syncthreads();
        sh[threadIdx.x] += t;
        __syncthreads();
    }
    int total = sh[1023];
    if (threadIdx.x == 0) {
        g_scan_val[b] = total;
        __threadfence();
        g_scan_flag[b] = 1;
    }
    if (threadIdx.x < 32) {
        int pre = 0;
        for (int p = b - 1 - (int)threadIdx.x; p >= 0; p -= 32) {
            while (g_scan_flag[p] == 0) {}
            pre += g_scan_val[p];
        }
#pragma unroll
        for (int off = 16; off > 0; off >>= 1)
            pre += __shfl_down_sync(0xffffffffu, pre, off);
        if (threadIdx.x == 0) {
            prefix_s = pre;
            if (b == NBLK - 1) g_rowptr[NN] = pre + total;
        }
    }
    __syncthreads();
    if (i < NN) {
        int excl = prefix_s + sh[threadIdx.x] - v;
        g_rowptr[i] = excl;
        g_cursor[i] = excl;
    }
}
__global__ void fill_kernel(const void* __restrict__ ei) {
    int e = blockIdx.x * blockDim.x + threadIdx.x;
    if (e >= NE) return;
    const int is64 = g_is64;
    int src = edge_idx(ei, e, is64);
    int dst = edge_idx(ei, (long long)NE + e, is64);
    if ((unsigned)src >= NN || (unsigned)dst >= NN) return;
    int pos = atomicAdd(&g_cursor[dst], 1);
    g_col[pos] = src;
}

// ---------------- CSR gathers ------------------------------------------------
__global__ void gather12_kernel(const float* __restrict__ x) {
    int n = (blockIdx.x * blockDim.x + threadIdx.x) >> 5;
    if (n >= NN) return;
    int lane = threadIdx.x & 31;
    int beg = g_rowptr[n], end = g_rowptr[n + 1];
    float acc = (lane < 12) ? x[(size_t)n * 12 + lane] : 0.f;
    for (int e = beg; e < end; e++) {
        int s = g_col[e];
        if (lane < 12) acc += x[(size_t)s * 12 + lane];
    }
    if (lane < 12) g_agg12[(size_t)n * 12 + lane] = acc;
}
// fp16 neighbor gather; emits PRE-SPLIT bf16 hi/lo A-tile images (a_off layout,
// no xor swizzle -> word index r*68 + lane*2 inside tile n>>7).
__global__ void gather128_h16_kernel(const __half* __restrict__ h16,
                                     const float* __restrict__ h) {
    int n = (blockIdx.x * blockDim.x + threadIdx.x) >> 5;
    if (n >= NN) return;
    int lane = threadIdx.x & 31;
    int beg = g_rowptr[n], end = g_rowptr[n + 1];
    const int fo = lane * 4;
    float4 acc = *reinterpret_cast<const float4*>(h + (size_t)n * D + fo);
    float4 acc2 = make_float4(0.f, 0.f, 0.f, 0.f);
    int e = beg;
    for (; e + 3 < end; e += 4) {
        int s0 = g_col[e], s1 = g_col[e + 1], s2 = g_col[e + 2], s3 = g_col[e + 3];
        uint2 p0 = *reinterpret_cast<const uint2*>(h16 + (size_t)s0 * D + fo);
        uint2 p1 = *reinterpret_cast<const uint2*>(h16 + (size_t)s1 * D + fo);
        uint2 p2 = *reinterpret_cast<const uint2*>(h16 + (size_t)s2 * D + fo);
        uint2 p3 = *reinterpret_cast<const uint2*>(h16 + (size_t)s3 * D + fo);
        acc_h2(acc, p0);  acc_h2(acc2, p1);
        acc_h2(acc, p2);  acc_h2(acc2, p3);
    }
    for (; e < end; e++) {
        uint2 p = *reinterpret_cast<const uint2*>(h16 + (size_t)g_col[e] * D + fo);
        acc_h2(acc, p);
    }
    acc.x += acc2.x; acc.y += acc2.y; acc.z += acc2.z; acc.w += acc2.w;
    uint32_t h0, l0, h1, l1;
    split2(acc.x, acc.y, h0, l0);
    split2(acc.z, acc.w, h1, l1);
    size_t w = (size_t)(n >> 7) * TILE_WORDS + (n & 127) * 68 + lane * 2;
    *reinterpret_cast<uint2*>(&g_aggHI[w]) = make_uint2(h0, h1);
    *reinterpret_cast<uint2*>(&g_aggLO[w]) = make_uint2(l0, l1);
}

// ============================================================================
// PERSISTENT mma.sync fused MLP: PGRID CTAs loop over 128-row tiles.
// W tiles cp.async'd ONCE per CTA; A tiles cp.async'd per tile from pre-split
// images when a16hi != nullptr (layers 2-5), else fp32 split path (layer1/head).
// 512 threads (16 warps, 4x4). bf16 hi/lo split, 3 passes, fp32 accum.
// ============================================================================
__device__ __forceinline__ void gemm_split(
    uint32_t aHi, uint32_t aLo, uint32_t wHi, uint32_t wLo,
    int r0, int cc, int n0, int lane, float acc[2][4][4], int kpad) {
#pragma unroll 2
    for (int kb = 0; kb < kpad; kb += 16) {
        uint32_t ah[2][4], al[2][4];
#pragma unroll
        for (int m = 0; m < 2; m++) {
            int rm = r0 + m * 16;
            ah[m][0] = lds32(aHi + a_off(rm,     kb + cc));
            ah[m][1] = lds32(aHi + a_off(rm + 8, kb + cc));
            ah[m][2] = lds32(aHi + a_off(rm,     kb + cc + 8));
            ah[m][3] = lds32(aHi + a_off(rm + 8, kb + cc + 8));
            al[m][0] = lds32(aLo + a_off(rm,     kb + cc));
            al[m][1] = lds32(aLo + a_off(rm + 8, kb + cc));
            al[m][2] = lds32(aLo + a_off(rm,     kb + cc + 8));
            al[m][3] = lds32(aLo + a_off(rm + 8, kb + cc + 8));
        }
#pragma unroll
        for (int t = 0; t < 4; t++) {
            int nl = n0 + t * 8 + (lane >> 2);
            uint32_t bh[2], bl[2];
            bh[0] = lds32(wHi + wt_off(nl, kb + cc));
            bh[1] = lds32(wHi + wt_off(nl, kb + cc + 8));
            bl[0] = lds32(wLo + wt_off(nl, kb + cc));
            bl[1] = lds32(wLo + wt_off(nl, kb + cc + 8));
            mma16816(acc[0][t], ah[0], bh);
            mma16816(acc[1][t], ah[1], bh);
            mma16816(acc[0][t], al[0], bh);
            mma16816(acc[1][t], al[1], bh);
            mma16816(acc[0][t], ah[0], bl);
            mma16816(acc[1][t], ah[1], bl);
        }
    }
}

template <int KIN, int KPAD>
__global__ __launch_bounds__(512, 1) void mlp_mma(
    const float* __restrict__ A,
    const uint32_t* __restrict__ a16hi, const uint32_t* __restrict__ a16lo,
    const uint32_t* __restrict__ w1hi, const uint32_t* __restrict__ w1lo,
    const uint32_t* __restrict__ w2hi, const uint32_t* __restrict__ w2lo,
    const float* __restrict__ b1,
    const float* __restrict__ W2f, const float* __restrict__ b2,
    const float* __restrict__ gamma, const float* __restrict__ beta,
    const float* __restrict__ mean, const float* __restrict__ var,
    float* __restrict__ out, __half* __restrict__ out16, int head) {
    extern __shared__ char smem[];
    const uint32_t sb = smem_to_u32(smem);
    const int tid = threadIdx.x;
    const int lane = tid & 31;
    const int wid = tid >> 5;
    const int wr = wid >> 2, wc = wid & 3;    // 4 x 4 warps

    const uint32_t AHI = sb + SM_AHI, ALO = sb + SM_ALO;
    const uint32_t W1HI = sb + SM_W1HI, W1LO = sb + SM_W1LO;
    const uint32_t W2HI = sb + SM_W2HI, W2LO = sb + SM_W2LO;
    float* par = (float*)(smem + SM_PAR);   // b1[128] b2[128] sc[128] mn[128] bt[128]

    // ---- ONCE: async W tile copies ----
    for (int i = tid; i < 2176; i += 512) {
        CP_ASYNC16(W1HI + i * 16, (const char*)w1hi + i * 16);
        CP_ASYNC16(W1LO + i * 16, (const char*)w1lo + i * 16);
    }
    if (!head) {
        for (int i = tid; i < 2176; i += 512) {
            CP_ASYNC16(W2HI + i * 16, (const char*)w2hi + i * 16);
            CP_ASYNC16(W2LO + i * 16, (const char*)w2lo + i * 16);
        }
    }
    CP_COMMIT();
    // ---- ONCE: head fc2 fp32, params ----
    if (head) {
        float* w2f = (float*)(smem + SM_W2HI);
        for (int i = tid; i < D * NCLS; i += 512) w2f[i] = __ldg(W2f + i);
    }
    if (tid < 128) {
        par[tid] = __ldg(b1 + tid);
        if (!head) {
            par[128 + tid] = __ldg(b2 + tid);
            par[256 + tid] = __ldg(gamma + tid) * rsqrtf(__ldg(var + tid) + 1e-5f);
            par[384 + tid] = __ldg(mean + tid);
            par[512 + tid] = __ldg(beta + tid);
        } else if (tid < NCLS) {
            par[128 + tid] = __ldg(b2 + tid);
        }
    }

    const int r0 = wr * 32 + (lane >> 2);
    const int cc = (lane & 3) * 2;
    const int n0 = wc * 32;
    bool wfirst = true;

    for (int tile = blockIdx.x; tile < NROWTILE; tile += gridDim.x) {
        const int row0 = tile * 128;

        // ---- stage A tiles ----
        if (a16hi != nullptr) {
            const char* srcHi = (const char*)(a16hi + (size_t)tile * TILE_WORDS);
            const char* srcLo = (const char*)(a16lo + (size_t)tile * TILE_WORDS);
            for (int i = tid; i < 2176; i += 512) {
                CP_ASYNC16(AHI + i * 16, srcHi + i * 16);
                CP_ASYNC16(ALO + i * 16, srcLo + i * 16);
            }
            CP_COMMIT();
            CP_WAIT(0);            // covers W group on first iteration too
            wfirst = false;
        } else {
            int r = tid >> 2, q = tid & 3;
            int gr = row0 + r;
            const float* ar = A + (size_t)gr * KIN;
            bool ok = gr < NN;
#pragma unroll
            for (int j = 0; j < KPAD / 16; j++) {
                int k = q * (KPAD / 4) + j * 4;
                float4 v = make_float4(0.f, 0.f, 0.f, 0.f);
                if (ok) {
                    if (k + 3 < KIN) v = *reinterpret_cast<const float4*>(ar + k);
                    else {
                        if (k     < KIN) v.x = ar[k];
                        if (k + 1 < KIN) v.y = ar[k + 1];
                        if (k + 2 < KIN) v.z = ar[k + 2];
                        if (k + 3 < KIN) v.w = ar[k + 3];
                    }
                }
                uint32_t h0, l0, h1, l1;
                split2(v.x, v.y, h0, l0);
                split2(v.z, v.w, h1, l1);
                sts32(AHI + a_off(r, k),     h0);
                sts32(AHI + a_off(r, k + 2), h1);
                sts32(ALO + a_off(r, k),     l0);
                sts32(ALO + a_off(r, k + 2), l1);
            }
            if (wfirst) { CP_WAIT(0); wfirst = false; }
        }
        __syncthreads();

        // ---- GEMM1 ----
        float acc[2][4][4];
#pragma unroll
        for (int m = 0; m < 2; m++)
#pragma unroll
            for (int t = 0; t < 4; t++)
#pragma unroll
                for (int j = 0; j < 4; j++) acc[m][t][j] = 0.f;
        gemm_split(AHI, ALO, W1HI, W1LO, r0, cc, n0, lane, acc, KPAD);
        __syncthreads();

        // ---- epilogue1: T = relu(acc + b1) -> back into A slots ----
        if (!head) {
#pragma unroll
            for (int m = 0; m < 2; m++) {
                int rm = r0 + m * 16;
#pragma unroll
                for (int t = 0; t < 4; t++) {
                    int c0 = n0 + t * 8 + cc;
                    float x0 = fmaxf(acc[m][t][0] + par[c0], 0.f);
                    float x1 = fmaxf(acc[m][t][1] + par[c0 + 1], 0.f);
                    float x2 = fmaxf(acc[m][t][2] + par[c0], 0.f);
                    float x3 = fmaxf(acc[m][t][3] + par[c0 + 1], 0.f);
                    uint32_t h, l;
                    split2(x0, x1, h, l);
                    sts32(AHI + a_off(rm, c0), h);
                    sts32(ALO + a_off(rm, c0), l);
                    split2(x2, x3, h, l);
                    sts32(AHI + a_off(rm + 8, c0), h);
                    sts32(ALO + a_off(rm + 8, c0), l);
                }
            }
        } else {
            float* Tf = (float*)(smem + SM_AHI);   // fp32, stride 132
#pragma unroll
            for (int m = 0; m < 2; m++) {
                int rm = r0 + m * 16;
#pragma unroll
                for (int t = 0; t < 4; t++) {
                    int c0 = n0 + t * 8 + cc;
                    Tf[rm * 132 + c0]           = fmaxf(acc[m][t][0] + par[c0], 0.f);
                    Tf[rm * 132 + c0 + 1]       = fmaxf(acc[m][t][1] + par[c0 + 1], 0.f);
                    Tf[(rm + 8) * 132 + c0]     = fmaxf(acc[m][t][2] + par[c0], 0.f);
                    Tf[(rm + 8) * 132 + c0 + 1] = fmaxf(acc[m][t][3] + par[c0 + 1], 0.f);
                }
            }
        }
        __syncthreads();

        if (head) {
            // ---- fc2 SIMT: out[128x6] = T @ W2f + b2 ----
            if (tid < 128) {
                const float* Tf = (const float*)(smem + SM_AHI);
                const float* Wf = (const float*)(smem + SM_W2HI);
                float a6[NCLS];
#pragma unroll
                for (int c = 0; c < NCLS; c++) a6[c] = par[128 + c];
                for (int kk = 0; kk < D; kk++) {
                    int k = (kk + lane) & (D - 1);
                    float tv = Tf[tid * 132 + k];
#pragma unroll
                    for (int c = 0; c < NCLS; c++) a6[c] += tv * Wf[k * NCLS + c];
                }
                if (row0 + tid < NN)
#pragma unroll
                    for (int c = 0; c < NCLS; c++)
                        out[(size_t)(row0 + tid) * NCLS + c] = a6[c];
            }
            __syncthreads();   // Tf reads done before next tile's A staging
            continue;
        }

        // ---- GEMM2 ----
#pragma unroll
        for (int m = 0; m < 2; m++)
#pragma unroll
            for (int t = 0; t < 4; t++)
#pragma unroll
                for (int j = 0; j < 4; j++) acc[m][t][j] = 0.f;
        gemm_split(AHI, ALO, W2HI, W2LO, r0, cc, n0, lane, acc, 128);

        // ---- epilogue2: BN(relu(acc + b2)) -> gmem fp32 + fp16 copy ----
#pragma unroll
        for (int m = 0; m < 2; m++) {
            int g0 = row0 + r0 + m * 16, g1 = g0 + 8;
#pragma unroll
            for (int t = 0; t < 4; t++) {
                int c0 = n0 + t * 8 + cc;
                float b0v = par[128 + c0], b1v = par[128 + c0 + 1];
                float s0 = par[256 + c0],  s1 = par[256 + c0 + 1];
                float m0 = par[384 + c0],  m1 = par[384 + c0 + 1];
                float t0 = par[512 + c0],  t1 = par[512 + c0 + 1];
                if (g0 < NN) {
                    float v0 = (fmaxf(acc[m][t][0] + b0v, 0.f) - m0) * s0 + t0;
                    float v1 = (fmaxf(acc[m][t][1] + b1v, 0.f) - m1) * s1 + t1;
                    *reinterpret_cast<float2*>(out + (size_t)g0 * D + c0) = make_float2(v0, v1);
                    *reinterpret_cast<__half2*>(out16 + (size_t)g0 * D + c0) =
                        __floats2half2_rn(v0, v1);
                }
                if (g1 < NN) {
                    float v2 = (fmaxf(acc[m][t][2] + b0v, 0.f) - m0) * s0 + t0;
                    float v3 = (fmaxf(acc[m][t][3] + b1v, 0.f) - m1) * s1 + t1;
                    *reinterpret_cast<float2*>(out + (size_t)g1 * D + c0) = make_float2(v2, v3);
                    *reinterpret_cast<__half2*>(out16 + (size_t)g1 * D + c0) =
                        __floats2half2_rn(v2, v3);
                }
            }
        }
        __syncthreads();   // GEMM2 smem reads done before next tile's A staging
    }
}

// ---------------- launch ----------------------------------------------------
extern "C" void kernel_launch(void* const* d_in, const int* in_sizes, int n_in,
                              void* d_out, int out_size) {
    const float* x      = (const float*)d_in[0];
    const void*  ei     = (const void*)d_in[1];
    const float* w1_0   = (const float*)d_in[2];
    const float* b1_0   = (const float*)d_in[3];
    const float* w2_0   = (const float*)d_in[4];
    const float* b2_0   = (const float*)d_in[5];
    const float* ws1    = (const float*)d_in[6];
    const float* bs1    = (const float*)d_in[7];
    const float* ws2    = (const float*)d_in[8];
    const float* bs2    = (const float*)d_in[9];
    const float* gammas = (const float*)d_in[10];
    const float* betas  = (const float*)d_in[11];
    const float* means  = (const float*)d_in[12];
    const float* vars   = (const float*)d_in[13];
    const float* fc1_w  = (const float*)d_in[14];
    const float* fc1_b  = (const float*)d_in[15];
    const float* fc2_w  = (const float*)d_in[16];
    const float* fc2_b  = (const float*)d_in[17];
    float* out = (float*)d_out;

    float *agg12, *hA, *hB;
    __half *h16A, *h16B;
    uint32_t *wt, *aggHI, *aggLO;
    cudaGetSymbolAddress((void**)&agg12, g_agg12);
    cudaGetSymbolAddress((void**)&hA, g_hA);
    cudaGetSymbolAddress((void**)&hB, g_hB);
    cudaGetSymbolAddress((void**)&h16A, g_h16A);
    cudaGetSymbolAddress((void**)&h16B, g_h16B);
    cudaGetSymbolAddress((void**)&wt, g_wt);
    cudaGetSymbolAddress((void**)&aggHI, g_aggHI);
    cudaGetSymbolAddress((void**)&aggLO, g_aggLO);
    auto tile = [&](int t, int half) -> const uint32_t* {
        return wt + ((size_t)t * 2 + half) * TILE_WORDS;
    };

    cudaFuncSetAttribute(mlp_mma<12, 16>, cudaFuncAttributeMaxDynamicSharedMemorySize, SM_TOTAL);
    cudaFuncSetAttribute(mlp_mma<128, 128>, cudaFuncAttributeMaxDynamicSharedMemorySize, SM_TOTAL);

    const int WARP_GRID = (NN * 32 + 255) / 256;      // one warp per node

    // ---- weight prep + CSR build ----
    prep_weights_kernel<<<(NTILES * 128 * 68 + 255) / 256, 256>>>(w1_0, w2_0, ws1, ws2, fc1_w);
    detect_zero_kernel<<<(NN + 255) / 256, 256>>>(ei);
    hist_kernel<<<(NE + 255) / 256, 256>>>(ei);
    scan_lookback_kernel<<<NBLK, 1024>>>();
    fill_kernel<<<(NE + 255) / 256, 256>>>(ei);

    // ---- layer 1 (nfeat=12): gather + MLP -> hA/h16A ----
    gather12_kernel<<<WARP_GRID, 256>>>(x);
    mlp_mma<12, 16><<<PGRID, 512, SM_TOTAL>>>(agg12, nullptr, nullptr,
                                              tile(0, 0), tile(0, 1), tile(1, 0), tile(1, 1),
                                              b1_0, nullptr, b2_0,
                                              gammas, betas, means, vars, hA, h16A, 0);

    // ---- layers 2-5: gather emits pre-split A images; MLP cp.asyncs them ----
    for (int i = 0; i < 4; i++) {
        const float*  hin   = (i & 1) ? hB   : hA;
        const __half* h16in = (i & 1) ? h16B : h16A;
        float*  hout   = (i & 1) ? hA   : hB;
        __half* h16out = (i & 1) ? h16A : h16B;
        gather128_h16_kernel<<<WARP_GRID, 256>>>(h16in, hin);
        mlp_mma<128, 128><<<PGRID, 512, SM_TOTAL>>>(nullptr, aggHI, aggLO,
                                                    tile(2 + 2 * i, 0), tile(2 + 2 * i, 1),
                                                    tile(3 + 2 * i, 0), tile(3 + 2 * i, 1),
                                                    bs1 + i * D, nullptr, bs2 + i * D,
                                                    gammas + (i + 1) * D, betas + (i + 1) * D,
                                                    means + (i + 1) * D, vars + (i + 1) * D,
                                                    hout, h16out, 0);
    }

    // ---- head: fc1 (mma, pre-split tile) + fc2 (SIMT fp32) ----
    mlp_mma<128, 128><<<PGRID, 512, SM_TOTAL>>>(hA, nullptr, nullptr,
                                                tile(10, 0), tile(10, 1),
                                                tile(10, 0), tile(10, 1),   // unused (head)
                                                fc1_b, fc2_w, fc2_b,
                                                nullptr, nullptr, nullptr, nullptr,
                                                out, nullptr, 1);
}